// round 1
// baseline (speedup 1.0000x reference)
#include <cuda_runtime.h>
#include <cstdint>

#define NN 100000
#define NE 3200000

// ---------------- scratch (static __device__, no allocation) ----------------
__device__ float g_buf0[(size_t)NN * 256];   // GEMM output (support)
__device__ float g_buf1[(size_t)NN * 256];   // SpMM output (activations)
__device__ int   g_rowptr[NN + 1];
__device__ int   g_cursor[NN];
__device__ int   g_esrc[NE];
__device__ float g_ew[NE];

// ---------------- CSR build ----------------
__global__ void zero_counts_kernel() {
    int i = blockIdx.x * blockDim.x + threadIdx.x;
    if (i < NN) g_cursor[i] = 0;
}

__global__ void hist_kernel(const int* __restrict__ dst) {
    int e = blockIdx.x * blockDim.x + threadIdx.x;
    if (e < NE) atomicAdd(&g_cursor[dst[e]], 1);
}

// single-block exclusive scan of g_cursor (counts) -> g_rowptr, init cursors
__global__ void scan_kernel() {
    __shared__ int sdata[1024];
    const int T = 1024;
    const int CH = (NN + T - 1) / T;  // 98
    int t = threadIdx.x;
    int base = t * CH;
    int s = 0;
    for (int i = 0; i < CH; i++) {
        int idx = base + i;
        if (idx < NN) s += g_cursor[idx];
    }
    sdata[t] = s;
    __syncthreads();
    // Hillis-Steele inclusive scan
    for (int off = 1; off < T; off <<= 1) {
        int v = (t >= off) ? sdata[t - off] : 0;
        __syncthreads();
        sdata[t] += v;
        __syncthreads();
    }
    int running = sdata[t] - s;  // exclusive prefix
    for (int i = 0; i < CH; i++) {
        int idx = base + i;
        if (idx < NN) {
            int c = g_cursor[idx];
            g_rowptr[idx] = running;
            g_cursor[idx] = running;  // scatter cursor
            running += c;
        }
    }
    if (t == 0) g_rowptr[NN] = NE;
}

__global__ void scatter_kernel(const int* __restrict__ src,
                               const int* __restrict__ dst,
                               const float* __restrict__ ew) {
    int e = blockIdx.x * blockDim.x + threadIdx.x;
    if (e < NE) {
        int d = dst[e];
        int pos = atomicAdd(&g_cursor[d], 1);
        g_esrc[pos] = src[e];
        g_ew[pos] = ew[e];
    }
}

// ---------------- GEMM: C[M,N] = A[M,K] @ B[K,N] ----------------
// 64x64 block tile, 16 K-step, 256 threads, 4x4 micro-tile.
template <int BM, int BN, int BK>
__global__ void gemm_kernel(const float* __restrict__ A,
                            const float* __restrict__ B,
                            float* __restrict__ C,
                            int M, int K, int N) {
    __shared__ float As[BK][BM];  // [k][m]
    __shared__ float Bs[BK][BN];  // [k][n]
    const int tid = threadIdx.x;               // 0..255
    const int tx = tid % (BN / 4);             // 0..15
    const int ty = tid / (BN / 4);             // 0..15
    const int row0 = blockIdx.x * BM;
    const int col0 = blockIdx.y * BN;

    float acc[4][4];
#pragma unroll
    for (int i = 0; i < 4; i++)
#pragma unroll
        for (int j = 0; j < 4; j++) acc[i][j] = 0.f;

    for (int k0 = 0; k0 < K; k0 += BK) {
        // load A tile (BM x BK): idx -> (m = idx/BK, k = idx%BK)
#pragma unroll
        for (int i = 0; i < (BM * BK) / 256; i++) {
            int idx = tid + i * 256;
            int m = idx / BK, kk = idx % BK;
            float v = 0.f;
            if (row0 + m < M) v = A[(size_t)(row0 + m) * K + k0 + kk];
            As[kk][m] = v;
        }
        // load B tile (BK x BN): idx -> (k = idx/BN, n = idx%BN), coalesced in n
#pragma unroll
        for (int i = 0; i < (BK * BN) / 256; i++) {
            int idx = tid + i * 256;
            int kk = idx / BN, n = idx % BN;
            float v = 0.f;
            if (col0 + n < N) v = B[(size_t)(k0 + kk) * N + col0 + n];
            Bs[kk][n] = v;
        }
        __syncthreads();
#pragma unroll
        for (int kk = 0; kk < BK; kk++) {
            float4 a4 = *reinterpret_cast<const float4*>(&As[kk][ty * 4]);
            float4 b4 = *reinterpret_cast<const float4*>(&Bs[kk][tx * 4]);
            float a[4] = {a4.x, a4.y, a4.z, a4.w};
            float b[4] = {b4.x, b4.y, b4.z, b4.w};
#pragma unroll
            for (int i = 0; i < 4; i++)
#pragma unroll
                for (int j = 0; j < 4; j++) acc[i][j] += a[i] * b[j];
        }
        __syncthreads();
    }

#pragma unroll
    for (int i = 0; i < 4; i++) {
        int m = row0 + ty * 4 + i;
        if (m >= M) continue;
#pragma unroll
        for (int j = 0; j < 4; j++) {
            int n = col0 + tx * 4 + j;
            if (n < N) C[(size_t)m * N + n] = acc[i][j];
        }
    }
}

// ---------------- SpMM gather: out[d] = relu(bias + sum_e w_e * sup[src_e]) ----
// one warp per dst node; float4 columns
template <int D>
__global__ void spmm_kernel(const float* __restrict__ sup,
                            const float* __restrict__ bias,
                            float* __restrict__ out) {
    const int warp = (blockIdx.x * blockDim.x + threadIdx.x) >> 5;
    const int lane = threadIdx.x & 31;
    if (warp >= NN) return;
    constexpr int G = D / 4;                  // float4 groups per row
    constexpr int NR = (G + 31) / 32;         // groups per lane
    float4 acc[NR];
#pragma unroll
    for (int r = 0; r < NR; r++) acc[r] = make_float4(0.f, 0.f, 0.f, 0.f);

    const int e0 = g_rowptr[warp];
    const int e1 = g_rowptr[warp + 1];
    for (int e = e0; e < e1; e++) {
        int s = g_esrc[e];
        float w = g_ew[e];
        const float4* srow = reinterpret_cast<const float4*>(sup + (size_t)s * D);
#pragma unroll
        for (int r = 0; r < NR; r++) {
            int g = lane + r * 32;
            if (g < G) {
                float4 f = srow[g];
                acc[r].x += w * f.x;
                acc[r].y += w * f.y;
                acc[r].z += w * f.z;
                acc[r].w += w * f.w;
            }
        }
    }
    float4* orow = reinterpret_cast<float4*>(out + (size_t)warp * D);
    const float4* brow = reinterpret_cast<const float4*>(bias);
#pragma unroll
    for (int r = 0; r < NR; r++) {
        int g = lane + r * 32;
        if (g < G) {
            float4 b = brow[g];
            float4 v;
            v.x = fmaxf(acc[r].x + b.x, 0.f);
            v.y = fmaxf(acc[r].y + b.y, 0.f);
            v.z = fmaxf(acc[r].z + b.z, 0.f);
            v.w = fmaxf(acc[r].w + b.w, 0.f);
            orow[g] = v;
        }
    }
}

// ---------------- log-softmax over 40 classes, warp per row ----------------
__global__ void lsm_kernel(const float* __restrict__ h, float* __restrict__ out) {
    const int warp = (blockIdx.x * blockDim.x + threadIdx.x) >> 5;
    const int lane = threadIdx.x & 31;
    if (warp >= NN) return;
    const float* row = h + (size_t)warp * 40;
    float v0 = row[lane];
    float v1 = (lane < 8) ? row[32 + lane] : -INFINITY;
    float m = fmaxf(v0, v1);
#pragma unroll
    for (int off = 16; off > 0; off >>= 1)
        m = fmaxf(m, __shfl_xor_sync(0xFFFFFFFFu, m, off));
    float s = expf(v0 - m) + ((lane < 8) ? expf(v1 - m) : 0.f);
#pragma unroll
    for (int off = 16; off > 0; off >>= 1)
        s += __shfl_xor_sync(0xFFFFFFFFu, s, off);
    float lse = logf(s);
    out[(size_t)warp * 40 + lane] = v0 - m - lse;
    if (lane < 8) out[(size_t)warp * 40 + 32 + lane] = v1 - m - lse;
}

// ---------------- launch ----------------
extern "C" void kernel_launch(void* const* d_in, const int* in_sizes, int n_in,
                              void* d_out, int out_size) {
    const float* x  = (const float*)d_in[0];
    const int* esrc = (const int*)d_in[1];
    const int* edst = (const int*)d_in[2];
    const float* ew = (const float*)d_in[3];
    const float* W1 = (const float*)d_in[4];
    const float* b1 = (const float*)d_in[5];
    const float* W2 = (const float*)d_in[6];
    const float* b2 = (const float*)d_in[7];
    const float* W3 = (const float*)d_in[8];
    const float* b3 = (const float*)d_in[9];
    const float* W4 = (const float*)d_in[10];
    const float* b4 = (const float*)d_in[11];
    float* out = (float*)d_out;

    float* buf0;  // support
    float* buf1;  // activations
    cudaGetSymbolAddress((void**)&buf0, g_buf0);
    cudaGetSymbolAddress((void**)&buf1, g_buf1);

    // --- CSR build (per-launch, deterministic offsets; bucket order atomic) ---
    zero_counts_kernel<<<(NN + 255) / 256, 256>>>();
    hist_kernel<<<(NE + 255) / 256, 256>>>(edst);
    scan_kernel<<<1, 1024>>>();
    scatter_kernel<<<(NE + 255) / 256, 256>>>(esrc, edst, ew);

    const int SPMM_BLOCKS = (NN * 32 + 255) / 256;  // warp per node

    // --- Layer 1: 512 -> 256 ---
    {
        dim3 grid((NN + 63) / 64, (256 + 63) / 64);
        gemm_kernel<64, 64, 16><<<grid, 256>>>(x, W1, buf0, NN, 512, 256);
        spmm_kernel<256><<<SPMM_BLOCKS, 256>>>(buf0, b1, buf1);
    }
    // --- Layer 2: 256 -> 128 ---
    {
        dim3 grid((NN + 63) / 64, (128 + 63) / 64);
        gemm_kernel<64, 64, 16><<<grid, 256>>>(buf1, W2, buf0, NN, 256, 128);
        spmm_kernel<128><<<SPMM_BLOCKS, 256>>>(buf0, b2, buf1);
    }
    // --- Layer 3: 128 -> 64 ---
    {
        dim3 grid((NN + 63) / 64, (64 + 63) / 64);
        gemm_kernel<64, 64, 16><<<grid, 256>>>(buf1, W3, buf0, NN, 128, 64);
        spmm_kernel<64><<<SPMM_BLOCKS, 256>>>(buf0, b3, buf1);
    }
    // --- Layer 4: 64 -> 40 ---
    {
        dim3 grid((NN + 63) / 64, (40 + 63) / 64);
        gemm_kernel<64, 64, 16><<<grid, 256>>>(buf1, W4, buf0, NN, 64, 40);
        spmm_kernel<40><<<SPMM_BLOCKS, 256>>>(buf0, b4, buf1);
    }
    // --- log-softmax ---
    lsm_kernel<<<SPMM_BLOCKS, 256>>>(buf1, out);
}

// round 4
// speedup vs baseline: 1.8704x; 1.8704x over previous
#include <cuda_runtime.h>
#include <cuda_fp16.h>
#include <cuda_bf16.h>
#include <cstdint>

#define NN 100000
#define NE 3200000
#define MP 100096   // 782 * 128 (padded rows)

// ================= scratch =================
__device__ uint16_t g_a_hi[(size_t)MP * 512];   // bf16 activations (hi)
__device__ uint16_t g_a_lo[(size_t)MP * 512];   // bf16 activations (lo)
__device__ uint16_t g_suph[(size_t)MP * 256];   // fp16 support (GEMM out)
__device__ float    g_h4[(size_t)MP * 40];      // fp32 layer-4 pre-softmax
__device__ uint16_t g_wh[180224];               // bf16 Wt hi (all layers)
__device__ uint16_t g_wl[180224];               // bf16 Wt lo
__device__ int   g_rowptr[NN + 1];
__device__ int   g_cursor[NN];
__device__ int   g_esrc[NE];
__device__ float g_ew[NE];

// ================= CSR build =================
__global__ void zero_counts_kernel() {
    int i = blockIdx.x * blockDim.x + threadIdx.x;
    if (i < NN) g_cursor[i] = 0;
}
__global__ void hist_kernel(const int* __restrict__ dst) {
    int e = blockIdx.x * blockDim.x + threadIdx.x;
    if (e < NE) atomicAdd(&g_cursor[dst[e]], 1);
}
__global__ void scan_kernel() {
    __shared__ int sdata[1024];
    const int T = 1024;
    const int CH = (NN + T - 1) / T;
    int t = threadIdx.x;
    int base = t * CH;
    int s = 0;
    for (int i = 0; i < CH; i++) { int idx = base + i; if (idx < NN) s += g_cursor[idx]; }
    sdata[t] = s;
    __syncthreads();
    for (int off = 1; off < T; off <<= 1) {
        int v = (t >= off) ? sdata[t - off] : 0;
        __syncthreads(); sdata[t] += v; __syncthreads();
    }
    int running = sdata[t] - s;
    for (int i = 0; i < CH; i++) {
        int idx = base + i;
        if (idx < NN) {
            int c = g_cursor[idx];
            g_rowptr[idx] = running;
            g_cursor[idx] = running;
            running += c;
        }
    }
    if (t == 0) g_rowptr[NN] = NE;
}
__global__ void scatter_kernel(const int* __restrict__ src, const int* __restrict__ dst,
                               const float* __restrict__ ew) {
    int e = blockIdx.x * blockDim.x + threadIdx.x;
    if (e < NE) {
        int d = dst[e];
        int pos = atomicAdd(&g_cursor[d], 1);
        g_esrc[pos] = src[e];
        g_ew[pos] = ew[e];
    }
}

// ================= bf16 hi/lo split kernels =================
__global__ void split_x_kernel(const float* __restrict__ x) {
    size_t i = (size_t)blockIdx.x * blockDim.x + threadIdx.x;
    if (i >= (size_t)MP * 512) return;
    size_t r = i >> 9;
    float v = (r < NN) ? x[i] : 0.f;
    __nv_bfloat16 h = __float2bfloat16(v);
    float res = v - __bfloat162float(h);
    __nv_bfloat16 l = __float2bfloat16(res);
    g_a_hi[i] = __nv_bfloat16_raw(h).x;
    g_a_lo[i] = __nv_bfloat16_raw(l).x;
}
// W [K,N] fp32 -> Wt [NPr,K] bf16 hi/lo (rows n>=N zeroed)
__global__ void split_w_kernel(const float* __restrict__ W, int K, int N, int NPr,
                               uint16_t* __restrict__ wh, uint16_t* __restrict__ wl) {
    int i = blockIdx.x * blockDim.x + threadIdx.x;
    if (i >= NPr * K) return;
    int n = i / K, k = i % K;
    float v = (n < N) ? W[(size_t)k * N + n] : 0.f;
    __nv_bfloat16 h = __float2bfloat16(v);
    float res = v - __bfloat162float(h);
    __nv_bfloat16 l = __float2bfloat16(res);
    wh[i] = __nv_bfloat16_raw(h).x;
    wl[i] = __nv_bfloat16_raw(l).x;
}

// ================= mma.sync helpers =================
__device__ __forceinline__ uint32_t smem_u32(const void* p) {
    uint32_t a;
    asm("{ .reg .u64 t; cvta.to.shared.u64 t, %1; cvt.u32.u64 %0, t; }" : "=r"(a) : "l"(p));
    return a;
}
__device__ __forceinline__ void ldsm_x4(uint32_t* r, uint32_t addr) {
    asm volatile("ldmatrix.sync.aligned.m8n8.x4.shared.b16 {%0,%1,%2,%3}, [%4];"
                 : "=r"(r[0]), "=r"(r[1]), "=r"(r[2]), "=r"(r[3]) : "r"(addr));
}
__device__ __forceinline__ void ldsm_x2(uint32_t* r, uint32_t addr) {
    asm volatile("ldmatrix.sync.aligned.m8n8.x2.shared.b16 {%0,%1}, [%2];"
                 : "=r"(r[0]), "=r"(r[1]) : "r"(addr));
}
__device__ __forceinline__ void mma_bf16(float* c, const uint32_t* a, const uint32_t* b) {
    asm volatile(
        "mma.sync.aligned.m16n8k16.row.col.f32.bf16.bf16.f32 "
        "{%0,%1,%2,%3}, {%4,%5,%6,%7}, {%8,%9}, {%0,%1,%2,%3};"
        : "+f"(c[0]), "+f"(c[1]), "+f"(c[2]), "+f"(c[3])
        : "r"(a[0]), "r"(a[1]), "r"(a[2]), "r"(a[3]), "r"(b[0]), "r"(b[1]));
}

// ================= HMMA GEMM =================
// sup[128 x NOUT slice] = A[128 x K] @ Bt[NP x K]^T using bf16 2-way split (3 mma terms).
// Block: 128(M) x 64(N) tile, 256 thr = 8 warps (2 M x 4 N), warp tile 64x16.
// SMEM: Ah/Al 128x64 bf16 (16KB each), Bh/Bl 64x64 bf16 (8KB each). KC=64.
__global__ __launch_bounds__(256)
void gemm_hmma_kernel(const uint16_t* __restrict__ Ah, const uint16_t* __restrict__ Al,
                      const uint16_t* __restrict__ Bh, const uint16_t* __restrict__ Bl,
                      __half* __restrict__ sup, int K, int NOUT) {
    extern __shared__ __align__(128) char smem[];
    const int OFF_AH = 0, OFF_AL = 16384, OFF_BH = 32768, OFF_BL = 40960;
    const uint32_t sb = smem_u32(smem);

    const int tid = threadIdx.x, wid = tid >> 5, lane = tid & 31;
    const int row0 = blockIdx.x * 128;
    const int nb0 = blockIdx.y * 64;          // block col offset into Bt rows
    const int wm = (wid & 1) * 64;            // warp M offset in tile
    const int wn = (wid >> 1) * 16;           // warp N offset in tile

    float acc[4][2][4];
#pragma unroll
    for (int i = 0; i < 4; i++)
#pragma unroll
        for (int j = 0; j < 2; j++)
#pragma unroll
            for (int q = 0; q < 4; q++) acc[i][j][q] = 0.f;

    // per-lane ldmatrix address components
    const int a_row_l = lane & 15;            // + wm + mf*16
    const int a_chl = lane >> 4;              // 0/1 -> k half chunk
    const int b_row_l = lane & 7;             // + wn + nf*8
    const int b_chl = (lane >> 3) & 1;

    const int CH = K >> 6;
    for (int c = 0; c < CH; ++c) {
        __syncthreads();
        const int kbase = c * 64;
        // load A tiles (128 rows x 8 chunks of 16B), swizzled: chunk' = cb ^ (r&7)
#pragma unroll
        for (int i = tid; i < 1024; i += 256) {
            int r = i >> 3, cb = i & 7;
            size_t gidx = (size_t)(row0 + r) * K + kbase + cb * 8;
            uint4 vh = *(const uint4*)(Ah + gidx);
            uint4 vl = *(const uint4*)(Al + gidx);
            uint32_t so = r * 128 + ((cb ^ (r & 7)) << 4);
            *(uint4*)(smem + OFF_AH + so) = vh;
            *(uint4*)(smem + OFF_AL + so) = vl;
        }
        // load B tiles (64 rows x 8 chunks)
#pragma unroll
        for (int i = tid; i < 512; i += 256) {
            int r = i >> 3, cb = i & 7;
            size_t gidx = (size_t)(nb0 + r) * K + kbase + cb * 8;
            uint4 vh = *(const uint4*)(Bh + gidx);
            uint4 vl = *(const uint4*)(Bl + gidx);
            uint32_t so = r * 128 + ((cb ^ (r & 7)) << 4);
            *(uint4*)(smem + OFF_BH + so) = vh;
            *(uint4*)(smem + OFF_BL + so) = vl;
        }
        __syncthreads();

#pragma unroll
        for (int ks = 0; ks < 4; ++ks) {
            uint32_t ah[4][4], al[4][4], bh[2][2], bl[2][2];
#pragma unroll
            for (int mf = 0; mf < 4; ++mf) {
                int r = wm + mf * 16 + a_row_l;
                uint32_t so = r * 128 + (((ks * 2 + a_chl) ^ (r & 7)) << 4);
                ldsm_x4(ah[mf], sb + OFF_AH + so);
                ldsm_x4(al[mf], sb + OFF_AL + so);
            }
#pragma unroll
            for (int nf = 0; nf < 2; ++nf) {
                int r = wn + nf * 8 + b_row_l;
                uint32_t so = r * 128 + (((ks * 2 + b_chl) ^ (r & 7)) << 4);
                ldsm_x2(bh[nf], sb + OFF_BH + so);
                ldsm_x2(bl[nf], sb + OFF_BL + so);
            }
#pragma unroll
            for (int mf = 0; mf < 4; ++mf)
#pragma unroll
                for (int nf = 0; nf < 2; ++nf) {
                    mma_bf16(acc[mf][nf], ah[mf], bh[nf]);
                    mma_bf16(acc[mf][nf], ah[mf], bl[nf]);
                    mma_bf16(acc[mf][nf], al[mf], bh[nf]);
                }
        }
    }

    // epilogue: fp16 store
    const int gid = lane >> 2, tid4 = lane & 3;
#pragma unroll
    for (int mf = 0; mf < 4; ++mf) {
#pragma unroll
        for (int nf = 0; nf < 2; ++nf) {
            int col = nb0 + wn + nf * 8 + tid4 * 2;
            if (col < NOUT) {
                int m0 = row0 + wm + mf * 16 + gid;
                __half2 h0 = __floats2half2_rn(acc[mf][nf][0], acc[mf][nf][1]);
                __half2 h1 = __floats2half2_rn(acc[mf][nf][2], acc[mf][nf][3]);
                *(__half2*)(sup + (size_t)m0 * NOUT + col) = h0;
                *(__half2*)(sup + (size_t)(m0 + 8) * NOUT + col) = h1;
            }
        }
    }
}

// ================= SpMM gather (fp16 support) =================
template <int D, bool LAST>
__global__ void spmm_kernel(const __half* __restrict__ sup, const float* __restrict__ bias,
                            uint16_t* __restrict__ act_hi, uint16_t* __restrict__ act_lo,
                            float* __restrict__ h4out) {
    const int warp = (blockIdx.x * blockDim.x + threadIdx.x) >> 5;
    const int lane = threadIdx.x & 31;
    if (warp >= NN) return;
    constexpr int G2 = D / 2;
    constexpr int NR = (G2 + 31) / 32;
    float2 acc[NR];
#pragma unroll
    for (int r = 0; r < NR; r++) acc[r] = make_float2(0.f, 0.f);

    const int e0 = g_rowptr[warp];
    const int e1 = g_rowptr[warp + 1];
    for (int e = e0; e < e1; e++) {
        int s = g_esrc[e];
        float w = g_ew[e];
        const __half2* srow = (const __half2*)(sup + (size_t)s * D);
#pragma unroll
        for (int r = 0; r < NR; r++) {
            int g = lane + r * 32;
            if (g < G2) {
                float2 f = __half22float2(srow[g]);
                acc[r].x += w * f.x;
                acc[r].y += w * f.y;
            }
        }
    }
    const float2* b2 = (const float2*)bias;
#pragma unroll
    for (int r = 0; r < NR; r++) {
        int g = lane + r * 32;
        if (g < G2) {
            float2 b = b2[g];
            float vx = fmaxf(acc[r].x + b.x, 0.f);
            float vy = fmaxf(acc[r].y + b.y, 0.f);
            if (LAST) {
                h4out[(size_t)warp * D + 2 * g] = vx;
                h4out[(size_t)warp * D + 2 * g + 1] = vy;
            } else {
                __nv_bfloat16 hx = __float2bfloat16(vx);
                __nv_bfloat16 hy = __float2bfloat16(vy);
                __nv_bfloat16 lx = __float2bfloat16(vx - __bfloat162float(hx));
                __nv_bfloat16 ly = __float2bfloat16(vy - __bfloat162float(hy));
                uint32_t hh = (uint32_t)__nv_bfloat16_raw(hx).x | ((uint32_t)__nv_bfloat16_raw(hy).x << 16);
                uint32_t ll = (uint32_t)__nv_bfloat16_raw(lx).x | ((uint32_t)__nv_bfloat16_raw(ly).x << 16);
                *(uint32_t*)(act_hi + (size_t)warp * D + 2 * g) = hh;
                *(uint32_t*)(act_lo + (size_t)warp * D + 2 * g) = ll;
            }
        }
    }
}

// ================= log-softmax (40 classes) =================
__global__ void lsm_kernel(const float* __restrict__ h, float* __restrict__ out) {
    const int warp = (blockIdx.x * blockDim.x + threadIdx.x) >> 5;
    const int lane = threadIdx.x & 31;
    if (warp >= NN) return;
    const float* row = h + (size_t)warp * 40;
    float v0 = row[lane];
    float v1 = (lane < 8) ? row[32 + lane] : -INFINITY;
    float m = fmaxf(v0, v1);
#pragma unroll
    for (int off = 16; off > 0; off >>= 1)
        m = fmaxf(m, __shfl_xor_sync(0xFFFFFFFFu, m, off));
    float s = expf(v0 - m) + ((lane < 8) ? expf(v1 - m) : 0.f);
#pragma unroll
    for (int off = 16; off > 0; off >>= 1)
        s += __shfl_xor_sync(0xFFFFFFFFu, s, off);
    float lse = logf(s);
    out[(size_t)warp * 40 + lane] = v0 - m - lse;
    if (lane < 8) out[(size_t)warp * 40 + 32 + lane] = v1 - m - lse;
}

// ================= launch =================
extern "C" void kernel_launch(void* const* d_in, const int* in_sizes, int n_in,
                              void* d_out, int out_size) {
    const float* x  = (const float*)d_in[0];
    const int* esrc = (const int*)d_in[1];
    const int* edst = (const int*)d_in[2];
    const float* ew = (const float*)d_in[3];
    const float* W1 = (const float*)d_in[4];
    const float* b1 = (const float*)d_in[5];
    const float* W2 = (const float*)d_in[6];
    const float* b2 = (const float*)d_in[7];
    const float* W3 = (const float*)d_in[8];
    const float* b3 = (const float*)d_in[9];
    const float* W4 = (const float*)d_in[10];
    const float* b4 = (const float*)d_in[11];
    float* out = (float*)d_out;

    uint16_t *ah, *al, *suph_u, *wh, *wl;
    float* h4;
    cudaGetSymbolAddress((void**)&ah, g_a_hi);
    cudaGetSymbolAddress((void**)&al, g_a_lo);
    cudaGetSymbolAddress((void**)&suph_u, g_suph);
    cudaGetSymbolAddress((void**)&h4, g_h4);
    cudaGetSymbolAddress((void**)&wh, g_wh);
    cudaGetSymbolAddress((void**)&wl, g_wl);
    __half* suph = (__half*)suph_u;

    // weight offsets: L1 256x512, L2 128x256, L3 64x128, L4 64x64
    const int WOFF1 = 0, WOFF2 = 131072, WOFF3 = 163840, WOFF4 = 172032;

    const int GSMEM = 49152;  // 16K+16K+8K+8K
    cudaFuncSetAttribute(gemm_hmma_kernel, cudaFuncAttributeMaxDynamicSharedMemorySize, GSMEM);

    // --- input + weight splits ---
    split_x_kernel<<<((size_t)MP * 512 + 255) / 256, 256>>>(x);
    split_w_kernel<<<(256 * 512 + 255) / 256, 256>>>(W1, 512, 256, 256, wh + WOFF1, wl + WOFF1);
    split_w_kernel<<<(128 * 256 + 255) / 256, 256>>>(W2, 256, 128, 128, wh + WOFF2, wl + WOFF2);
    split_w_kernel<<<(64 * 128 + 255) / 256, 256>>>(W3, 128, 64, 64, wh + WOFF3, wl + WOFF3);
    split_w_kernel<<<(64 * 64 + 255) / 256, 256>>>(W4, 64, 40, 64, wh + WOFF4, wl + WOFF4);

    // --- CSR build ---
    zero_counts_kernel<<<(NN + 255) / 256, 256>>>();
    hist_kernel<<<(NE + 255) / 256, 256>>>(edst);
    scan_kernel<<<1, 1024>>>();
    scatter_kernel<<<(NE + 255) / 256, 256>>>(esrc, edst, ew);

    const int GX = MP / 128;  // 782
    const int SPMM_BLOCKS = (NN * 32 + 255) / 256;

    // --- Layer 1: 512 -> 256 ---
    gemm_hmma_kernel<<<dim3(GX, 4), 256, GSMEM>>>(ah, al, wh + WOFF1, wl + WOFF1, suph, 512, 256);
    spmm_kernel<256, false><<<SPMM_BLOCKS, 256>>>(suph, b1, ah, al, nullptr);
    // --- Layer 2: 256 -> 128 ---
    gemm_hmma_kernel<<<dim3(GX, 2), 256, GSMEM>>>(ah, al, wh + WOFF2, wl + WOFF2, suph, 256, 128);
    spmm_kernel<128, false><<<SPMM_BLOCKS, 256>>>(suph, b2, ah, al, nullptr);
    // --- Layer 3: 128 -> 64 ---
    gemm_hmma_kernel<<<dim3(GX, 1), 256, GSMEM>>>(ah, al, wh + WOFF3, wl + WOFF3, suph, 128, 64);
    spmm_kernel<64, false><<<SPMM_BLOCKS, 256>>>(suph, b3, ah, al, nullptr);
    // --- Layer 4: 64 -> 40 ---
    gemm_hmma_kernel<<<dim3(GX, 1), 256, GSMEM>>>(ah, al, wh + WOFF4, wl + WOFF4, suph, 64, 40);
    spmm_kernel<40, true><<<SPMM_BLOCKS, 256>>>(suph, b4, nullptr, nullptr, h4);
    // --- log-softmax ---
    lsm_kernel<<<SPMM_BLOCKS, 256>>>(h4, out);
}

// round 7
// speedup vs baseline: 2.4617x; 1.3161x over previous
#include <cuda_runtime.h>
#include <cuda_fp16.h>
#include <cuda_bf16.h>
#include <cstdint>

#define NN 100000
#define NE 3200000
#define MP 100096   // 782 * 128 (padded rows)

// ================= scratch =================
__device__ uint16_t g_a_hi[(size_t)MP * 512];   // bf16 activations (hi)
__device__ uint16_t g_a_lo[(size_t)MP * 512];   // bf16 activations (lo)
__device__ uint16_t g_suph[(size_t)MP * 256];   // fp16 support (GEMM out)
__device__ float    g_h4[(size_t)MP * 40];      // fp32 layer-4 pre-softmax
__device__ uint16_t g_wh[180224];               // bf16 Wt hi (all layers)
__device__ uint16_t g_wl[180224];               // bf16 Wt lo
__device__ int   g_rowptr[NN + 1];
__device__ int   g_cursor[NN];
__device__ int   g_esrc[NE];
__device__ float g_ew[NE];

// ================= CSR build =================
__global__ void zero_counts_kernel() {
    int i = blockIdx.x * blockDim.x + threadIdx.x;
    if (i < NN) g_cursor[i] = 0;
}
__global__ void hist_kernel(const int* __restrict__ dst) {
    int e = blockIdx.x * blockDim.x + threadIdx.x;
    if (e < NE) atomicAdd(&g_cursor[dst[e]], 1);
}
__global__ void scan_kernel() {
    __shared__ int sdata[1024];
    const int T = 1024;
    const int CH = (NN + T - 1) / T;
    int t = threadIdx.x;
    int base = t * CH;
    int s = 0;
    for (int i = 0; i < CH; i++) { int idx = base + i; if (idx < NN) s += g_cursor[idx]; }
    sdata[t] = s;
    __syncthreads();
    for (int off = 1; off < T; off <<= 1) {
        int v = (t >= off) ? sdata[t - off] : 0;
        __syncthreads(); sdata[t] += v; __syncthreads();
    }
    int running = sdata[t] - s;
    for (int i = 0; i < CH; i++) {
        int idx = base + i;
        if (idx < NN) {
            int c = g_cursor[idx];
            g_rowptr[idx] = running;
            g_cursor[idx] = running;
            running += c;
        }
    }
    if (t == 0) g_rowptr[NN] = NE;
}
__global__ void scatter_kernel(const int* __restrict__ src, const int* __restrict__ dst,
                               const float* __restrict__ ew) {
    int e = blockIdx.x * blockDim.x + threadIdx.x;
    if (e < NE) {
        int d = dst[e];
        int pos = atomicAdd(&g_cursor[d], 1);
        g_esrc[pos] = src[e];
        g_ew[pos] = ew[e];
    }
}

// ================= bf16 hi/lo split kernels =================
__global__ void split_x_kernel(const float* __restrict__ x) {
    size_t i = (size_t)blockIdx.x * blockDim.x + threadIdx.x;
    if (i >= (size_t)MP * 512) return;
    size_t r = i >> 9;
    float v = (r < NN) ? x[i] : 0.f;
    __nv_bfloat16 h = __float2bfloat16(v);
    float res = v - __bfloat162float(h);
    __nv_bfloat16 l = __float2bfloat16(res);
    g_a_hi[i] = __nv_bfloat16_raw(h).x;
    g_a_lo[i] = __nv_bfloat16_raw(l).x;
}
__global__ void split_w_kernel(const float* __restrict__ W, int K, int N, int NPr,
                               uint16_t* __restrict__ wh, uint16_t* __restrict__ wl) {
    int i = blockIdx.x * blockDim.x + threadIdx.x;
    if (i >= NPr * K) return;
    int n = i / K, k = i % K;
    float v = (n < N) ? W[(size_t)k * N + n] : 0.f;
    __nv_bfloat16 h = __float2bfloat16(v);
    float res = v - __bfloat162float(h);
    __nv_bfloat16 l = __float2bfloat16(res);
    wh[i] = __nv_bfloat16_raw(h).x;
    wl[i] = __nv_bfloat16_raw(l).x;
}

// ================= mma.sync / cp.async helpers =================
__device__ __forceinline__ uint32_t smem_u32(const void* p) {
    uint32_t a;
    asm("{ .reg .u64 t; cvta.to.shared.u64 t, %1; cvt.u32.u64 %0, t; }" : "=r"(a) : "l"(p));
    return a;
}
__device__ __forceinline__ void ldsm_x4(uint32_t* r, uint32_t addr) {
    asm volatile("ldmatrix.sync.aligned.m8n8.x4.shared.b16 {%0,%1,%2,%3}, [%4];"
                 : "=r"(r[0]), "=r"(r[1]), "=r"(r[2]), "=r"(r[3]) : "r"(addr));
}
__device__ __forceinline__ void ldsm_x2(uint32_t* r, uint32_t addr) {
    asm volatile("ldmatrix.sync.aligned.m8n8.x2.shared.b16 {%0,%1}, [%2];"
                 : "=r"(r[0]), "=r"(r[1]) : "r"(addr));
}
__device__ __forceinline__ void mma_bf16(float* c, const uint32_t* a, const uint32_t* b) {
    asm volatile(
        "mma.sync.aligned.m16n8k16.row.col.f32.bf16.bf16.f32 "
        "{%0,%1,%2,%3}, {%4,%5,%6,%7}, {%8,%9}, {%0,%1,%2,%3};"
        : "+f"(c[0]), "+f"(c[1]), "+f"(c[2]), "+f"(c[3])
        : "r"(a[0]), "r"(a[1]), "r"(a[2]), "r"(a[3]), "r"(b[0]), "r"(b[1]));
}
__device__ __forceinline__ void cp16(uint32_t saddr, const void* gptr) {
    asm volatile("cp.async.cg.shared.global [%0], [%1], 16;" :: "r"(saddr), "l"(gptr));
}
__device__ __forceinline__ void cp_commit() { asm volatile("cp.async.commit_group;"); }
template <int N>
__device__ __forceinline__ void cp_wait() { asm volatile("cp.async.wait_group %0;" :: "n"(N)); }

// ================= HMMA GEMM (2-stage cp.async pipeline) =================
// sup[128 x NOUT slice] = A[128 x K] @ Bt[NP x K]^T, bf16 2-way split (3 mma terms).
// Block 128(M) x 64(N), 8 warps (2M x 4N), warp tile 64x16, KC=64.
// blockIdx.x = N block (so consecutive CTAs share A rows), blockIdx.y = M block.
#define G_STAGE 49152
#define G_OFF_AH 0
#define G_OFF_AL 16384
#define G_OFF_BH 32768
#define G_OFF_BL 40960
__global__ __launch_bounds__(256)
void gemm_hmma_kernel(const uint16_t* __restrict__ Ah, const uint16_t* __restrict__ Al,
                      const uint16_t* __restrict__ Bh, const uint16_t* __restrict__ Bl,
                      __half* __restrict__ sup, int K, int NOUT) {
    extern __shared__ __align__(128) char smem[];
    const uint32_t sb = smem_u32(smem);
    const int tid = threadIdx.x, wid = tid >> 5, lane = tid & 31;
    const int row0 = blockIdx.y * 128;
    const int nb0 = blockIdx.x * 64;
    const int wm = (wid & 1) * 64;
    const int wn = (wid >> 1) * 16;

    float acc[4][2][4];
#pragma unroll
    for (int i = 0; i < 4; i++)
#pragma unroll
        for (int j = 0; j < 2; j++)
#pragma unroll
            for (int q = 0; q < 4; q++) acc[i][j][q] = 0.f;

    const int a_row_l = lane & 15;
    const int a_chl = lane >> 4;
    const int b_row_l = lane & 7;
    const int b_chl = (lane >> 3) & 1;
    const int CH = K >> 6;

    // stage loader: 12 cp.async per thread
    auto load_stage = [&](int c, int buf) {
        const int kbase = c * 64;
        const uint32_t so_base = sb + buf * G_STAGE;
#pragma unroll
        for (int i = tid; i < 1024; i += 256) {
            int r = i >> 3, cb = i & 7;
            size_t gidx = (size_t)(row0 + r) * K + kbase + cb * 8;
            uint32_t so = r * 128 + ((cb ^ (r & 7)) << 4);
            cp16(so_base + G_OFF_AH + so, Ah + gidx);
            cp16(so_base + G_OFF_AL + so, Al + gidx);
        }
#pragma unroll
        for (int i = tid; i < 512; i += 256) {
            int r = i >> 3, cb = i & 7;
            size_t gidx = (size_t)(nb0 + r) * K + kbase + cb * 8;
            uint32_t so = r * 128 + ((cb ^ (r & 7)) << 4);
            cp16(so_base + G_OFF_BH + so, Bh + gidx);
            cp16(so_base + G_OFF_BL + so, Bl + gidx);
        }
        cp_commit();
    };

    load_stage(0, 0);
    for (int c = 0; c < CH; ++c) {
        if (c + 1 < CH) { load_stage(c + 1, (c + 1) & 1); cp_wait<1>(); }
        else cp_wait<0>();
        __syncthreads();

        const uint32_t stb = sb + (c & 1) * G_STAGE;
#pragma unroll
        for (int ks = 0; ks < 4; ++ks) {
            uint32_t ah[4][4], al[4][4], bh[2][2], bl[2][2];
#pragma unroll
            for (int mf = 0; mf < 4; ++mf) {
                int r = wm + mf * 16 + a_row_l;
                uint32_t so = r * 128 + (((ks * 2 + a_chl) ^ (r & 7)) << 4);
                ldsm_x4(ah[mf], stb + G_OFF_AH + so);
                ldsm_x4(al[mf], stb + G_OFF_AL + so);
            }
#pragma unroll
            for (int nf = 0; nf < 2; ++nf) {
                int r = wn + nf * 8 + b_row_l;
                uint32_t so = r * 128 + (((ks * 2 + b_chl) ^ (r & 7)) << 4);
                ldsm_x2(bh[nf], stb + G_OFF_BH + so);
                ldsm_x2(bl[nf], stb + G_OFF_BL + so);
            }
#pragma unroll
            for (int mf = 0; mf < 4; ++mf)
#pragma unroll
                for (int nf = 0; nf < 2; ++nf) {
                    mma_bf16(acc[mf][nf], ah[mf], bh[nf]);
                    mma_bf16(acc[mf][nf], ah[mf], bl[nf]);
                    mma_bf16(acc[mf][nf], al[mf], bh[nf]);
                }
        }
        __syncthreads();
    }

    const int gid = lane >> 2, tid4 = lane & 3;
#pragma unroll
    for (int mf = 0; mf < 4; ++mf) {
#pragma unroll
        for (int nf = 0; nf < 2; ++nf) {
            int col = nb0 + wn + nf * 8 + tid4 * 2;
            if (col < NOUT) {
                int m0 = row0 + wm + mf * 16 + gid;
                __half2 h0 = __floats2half2_rn(acc[mf][nf][0], acc[mf][nf][1]);
                __half2 h1 = __floats2half2_rn(acc[mf][nf][2], acc[mf][nf][3]);
                *(__half2*)(sup + (size_t)m0 * NOUT + col) = h0;
                *(__half2*)(sup + (size_t)(m0 + 8) * NOUT + col) = h1;
            }
        }
    }
}

// ================= SpMM gather (fp16 support, 16B/lane, multi-edge) =================
// D in {256,128,64}: lpe = D/8 lanes per edge (16B each), epi = 32/lpe edges in flight.
template <int D>
__global__ void spmm_vec_kernel(const __half* __restrict__ sup, const float* __restrict__ bias,
                                uint16_t* __restrict__ act_hi, uint16_t* __restrict__ act_lo) {
    constexpr int LPE = D / 8;         // lanes covering one row
    constexpr int EPI = 32 / LPE;      // edges per iteration
    const int warp = (blockIdx.x * blockDim.x + threadIdx.x) >> 5;
    const int lane = threadIdx.x & 31;
    if (warp >= NN) return;
    const int sub = lane / LPE;        // which edge in the group
    const int seg = lane % LPE;        // 16B segment within the row

    float acc[8];
#pragma unroll
    for (int q = 0; q < 8; q++) acc[q] = 0.f;

    const int e0 = g_rowptr[warp];
    const int e1 = g_rowptr[warp + 1];
    for (int e = e0; e < e1; e += EPI) {
        int my_e = e + sub;
        if (my_e < e1) {
            int s = g_esrc[my_e];
            float w = g_ew[my_e];
            uint4 v = *((const uint4*)(sup + (size_t)s * D) + seg);
            float2 f0 = __half22float2(*(__half2*)&v.x);
            float2 f1 = __half22float2(*(__half2*)&v.y);
            float2 f2 = __half22float2(*(__half2*)&v.z);
            float2 f3 = __half22float2(*(__half2*)&v.w);
            acc[0] += w * f0.x; acc[1] += w * f0.y;
            acc[2] += w * f1.x; acc[3] += w * f1.y;
            acc[4] += w * f2.x; acc[5] += w * f2.y;
            acc[6] += w * f3.x; acc[7] += w * f3.y;
        }
    }
    // combine partials of the EPI sub-edges (lanes seg, seg+LPE, ...)
#pragma unroll
    for (int off = LPE; off < 32; off <<= 1)
#pragma unroll
        for (int q = 0; q < 8; q++)
            acc[q] += __shfl_xor_sync(0xFFFFFFFFu, acc[q], off);

    if (lane < LPE) {
        int col0 = lane * 8;
        uint32_t hh[4], ll[4];
#pragma unroll
        for (int q = 0; q < 8; q += 2) {
            float vx = fmaxf(acc[q] + bias[col0 + q], 0.f);
            float vy = fmaxf(acc[q + 1] + bias[col0 + q + 1], 0.f);
            __nv_bfloat16 hx = __float2bfloat16(vx);
            __nv_bfloat16 hy = __float2bfloat16(vy);
            __nv_bfloat16 lx = __float2bfloat16(vx - __bfloat162float(hx));
            __nv_bfloat16 ly = __float2bfloat16(vy - __bfloat162float(hy));
            hh[q >> 1] = (uint32_t)__nv_bfloat16_raw(hx).x | ((uint32_t)__nv_bfloat16_raw(hy).x << 16);
            ll[q >> 1] = (uint32_t)__nv_bfloat16_raw(lx).x | ((uint32_t)__nv_bfloat16_raw(ly).x << 16);
        }
        *(uint4*)(act_hi + (size_t)warp * D + col0) = make_uint4(hh[0], hh[1], hh[2], hh[3]);
        *(uint4*)(act_lo + (size_t)warp * D + col0) = make_uint4(ll[0], ll[1], ll[2], ll[3]);
    }
}

// last layer: D=40, fp32 out
__global__ void spmm_last_kernel(const __half* __restrict__ sup, const float* __restrict__ bias,
                                 float* __restrict__ h4out) {
    const int warp = (blockIdx.x * blockDim.x + threadIdx.x) >> 5;
    const int lane = threadIdx.x & 31;
    if (warp >= NN) return;
    float2 acc = make_float2(0.f, 0.f);
    const int e0 = g_rowptr[warp];
    const int e1 = g_rowptr[warp + 1];
    for (int e = e0; e < e1; e++) {
        int s = g_esrc[e];
        float w = g_ew[e];
        if (lane < 20) {
            float2 f = __half22float2(((const __half2*)(sup + (size_t)s * 40))[lane]);
            acc.x += w * f.x;
            acc.y += w * f.y;
        }
    }
    if (lane < 20) {
        float vx = fmaxf(acc.x + bias[2 * lane], 0.f);
        float vy = fmaxf(acc.y + bias[2 * lane + 1], 0.f);
        h4out[(size_t)warp * 40 + 2 * lane] = vx;
        h4out[(size_t)warp * 40 + 2 * lane + 1] = vy;
    }
}

// ================= log-softmax (40 classes) =================
__global__ void lsm_kernel(const float* __restrict__ h, float* __restrict__ out) {
    const int warp = (blockIdx.x * blockDim.x + threadIdx.x) >> 5;
    const int lane = threadIdx.x & 31;
    if (warp >= NN) return;
    const float* row = h + (size_t)warp * 40;
    float v0 = row[lane];
    float v1 = (lane < 8) ? row[32 + lane] : -INFINITY;
    float m = fmaxf(v0, v1);
#pragma unroll
    for (int off = 16; off > 0; off >>= 1)
        m = fmaxf(m, __shfl_xor_sync(0xFFFFFFFFu, m, off));
    float s = expf(v0 - m) + ((lane < 8) ? expf(v1 - m) : 0.f);
#pragma unroll
    for (int off = 16; off > 0; off >>= 1)
        s += __shfl_xor_sync(0xFFFFFFFFu, s, off);
    float lse = logf(s);
    out[(size_t)warp * 40 + lane] = v0 - m - lse;
    if (lane < 8) out[(size_t)warp * 40 + 32 + lane] = v1 - m - lse;
}

// ================= launch =================
extern "C" void kernel_launch(void* const* d_in, const int* in_sizes, int n_in,
                              void* d_out, int out_size) {
    const float* x  = (const float*)d_in[0];
    const int* esrc = (const int*)d_in[1];
    const int* edst = (const int*)d_in[2];
    const float* ew = (const float*)d_in[3];
    const float* W1 = (const float*)d_in[4];
    const float* b1 = (const float*)d_in[5];
    const float* W2 = (const float*)d_in[6];
    const float* b2 = (const float*)d_in[7];
    const float* W3 = (const float*)d_in[8];
    const float* b3 = (const float*)d_in[9];
    const float* W4 = (const float*)d_in[10];
    const float* b4 = (const float*)d_in[11];
    float* out = (float*)d_out;

    uint16_t *ah, *al, *suph_u, *wh, *wl;
    float* h4;
    cudaGetSymbolAddress((void**)&ah, g_a_hi);
    cudaGetSymbolAddress((void**)&al, g_a_lo);
    cudaGetSymbolAddress((void**)&suph_u, g_suph);
    cudaGetSymbolAddress((void**)&h4, g_h4);
    cudaGetSymbolAddress((void**)&wh, g_wh);
    cudaGetSymbolAddress((void**)&wl, g_wl);
    __half* suph = (__half*)suph_u;

    const int WOFF1 = 0, WOFF2 = 131072, WOFF3 = 163840, WOFF4 = 172032;

    const int GSMEM = 2 * G_STAGE;  // 96KB, 2-stage
    cudaFuncSetAttribute(gemm_hmma_kernel, cudaFuncAttributeMaxDynamicSharedMemorySize, GSMEM);

    // side stream for the CSR build (parallel branch in the captured graph)
    static cudaStream_t s2 = nullptr;
    static cudaEvent_t ev_fork = nullptr, ev_join = nullptr;
    if (!s2) {
        cudaStreamCreateWithFlags(&s2, cudaStreamNonBlocking);
        cudaEventCreateWithFlags(&ev_fork, cudaEventDisableTiming);
        cudaEventCreateWithFlags(&ev_join, cudaEventDisableTiming);
    }

    cudaEventRecord(ev_fork, 0);
    cudaStreamWaitEvent(s2, ev_fork, 0);
    // --- CSR build on s2 ---
    zero_counts_kernel<<<(NN + 255) / 256, 256, 0, s2>>>();
    hist_kernel<<<(NE + 255) / 256, 256, 0, s2>>>(edst);
    scan_kernel<<<1, 1024, 0, s2>>>();
    scatter_kernel<<<(NE + 255) / 256, 256, 0, s2>>>(esrc, edst, ew);
    cudaEventRecord(ev_join, s2);

    // --- main chain: splits + layer-1 GEMM ---
    split_x_kernel<<<((size_t)MP * 512 + 255) / 256, 256>>>(x);
    split_w_kernel<<<(256 * 512 + 255) / 256, 256>>>(W1, 512, 256, 256, wh + WOFF1, wl + WOFF1);
    split_w_kernel<<<(128 * 256 + 255) / 256, 256>>>(W2, 256, 128, 128, wh + WOFF2, wl + WOFF2);
    split_w_kernel<<<(64 * 128 + 255) / 256, 256>>>(W3, 128, 64, 64, wh + WOFF3, wl + WOFF3);
    split_w_kernel<<<(64 * 64 + 255) / 256, 256>>>(W4, 64, 40, 64, wh + WOFF4, wl + WOFF4);

    const int GY = MP / 128;  // 782
    const int SPMM_BLOCKS = (NN * 32 + 255) / 256;

    gemm_hmma_kernel<<<dim3(4, GY), 256, GSMEM>>>(ah, al, wh + WOFF1, wl + WOFF1, suph, 512, 256);
    cudaStreamWaitEvent(0, ev_join, 0);  // SpMM needs the CSR
    spmm_vec_kernel<256><<<SPMM_BLOCKS, 256>>>(suph, b1, ah, al);

    gemm_hmma_kernel<<<dim3(2, GY), 256, GSMEM>>>(ah, al, wh + WOFF2, wl + WOFF2, suph, 256, 128);
    spmm_vec_kernel<128><<<SPMM_BLOCKS, 256>>>(suph, b2, ah, al);

    gemm_hmma_kernel<<<dim3(1, GY), 256, GSMEM>>>(ah, al, wh + WOFF3, wl + WOFF3, suph, 128, 64);
    spmm_vec_kernel<64><<<SPMM_BLOCKS, 256>>>(suph, b3, ah, al);

    gemm_hmma_kernel<<<dim3(1, GY), 256, GSMEM>>>(ah, al, wh + WOFF4, wl + WOFF4, suph, 64, 40);
    spmm_last_kernel<<<SPMM_BLOCKS, 256>>>(suph, b4, h4);

    lsm_kernel<<<SPMM_BLOCKS, 256>>>(h4, out);
}

// round 8
// speedup vs baseline: 2.8785x; 1.1693x over previous
#include <cuda_runtime.h>
#include <cuda_fp16.h>
#include <cuda_bf16.h>
#include <cstdint>

#define NN 100000
#define NE 3200000
#define MP 100096   // 782 * 128 (padded rows)

// ================= scratch =================
__device__ uint16_t g_a_hi[(size_t)MP * 512];   // bf16 activations (hi)
__device__ uint16_t g_a_lo[(size_t)MP * 512];   // bf16 activations (lo)
__device__ uint16_t g_suph[(size_t)MP * 256];   // fp16 support (GEMM out)
__device__ uint16_t g_wh[180224];               // bf16 Wt hi (all layers)
__device__ uint16_t g_wl[180224];               // bf16 Wt lo
__device__ int   g_rowptr[NN + 1];
__device__ int   g_cursor[NN];
__device__ int   g_esrc[NE];
__device__ float g_ew[NE];

// ================= CSR build =================
__global__ void zero_counts_kernel() {
    int i = blockIdx.x * blockDim.x + threadIdx.x;
    if (i < NN) g_cursor[i] = 0;
}
__global__ void hist_kernel(const int* __restrict__ dst) {
    int e = blockIdx.x * blockDim.x + threadIdx.x;
    if (e < NE) atomicAdd(&g_cursor[dst[e]], 1);
}
__global__ void scan_kernel() {
    __shared__ int sdata[1024];
    const int T = 1024;
    const int CH = (NN + T - 1) / T;
    int t = threadIdx.x;
    int base = t * CH;
    int s = 0;
    for (int i = 0; i < CH; i++) { int idx = base + i; if (idx < NN) s += g_cursor[idx]; }
    sdata[t] = s;
    __syncthreads();
    for (int off = 1; off < T; off <<= 1) {
        int v = (t >= off) ? sdata[t - off] : 0;
        __syncthreads(); sdata[t] += v; __syncthreads();
    }
    int running = sdata[t] - s;
    for (int i = 0; i < CH; i++) {
        int idx = base + i;
        if (idx < NN) {
            int c = g_cursor[idx];
            g_rowptr[idx] = running;
            g_cursor[idx] = running;
            running += c;
        }
    }
    if (t == 0) g_rowptr[NN] = NE;
}
__global__ void scatter_kernel(const int* __restrict__ src, const int* __restrict__ dst,
                               const float* __restrict__ ew) {
    int e = blockIdx.x * blockDim.x + threadIdx.x;
    if (e < NE) {
        int d = dst[e];
        int pos = atomicAdd(&g_cursor[d], 1);
        g_esrc[pos] = src[e];
        g_ew[pos] = ew[e];
    }
}

// ================= bf16 hi/lo split helpers =================
__device__ __forceinline__ void split2(float f0, float f1, uint32_t& hi, uint32_t& lo) {
    __nv_bfloat16 h0 = __float2bfloat16(f0), h1 = __float2bfloat16(f1);
    float r0 = f0 - __bfloat162float(h0), r1 = f1 - __bfloat162float(h1);
    __nv_bfloat16 l0 = __float2bfloat16(r0), l1 = __float2bfloat16(r1);
    hi = (uint32_t)__nv_bfloat16_raw(h0).x | ((uint32_t)__nv_bfloat16_raw(h1).x << 16);
    lo = (uint32_t)__nv_bfloat16_raw(l0).x | ((uint32_t)__nv_bfloat16_raw(l1).x << 16);
}

__global__ void split_w_kernel(const float* __restrict__ W, int K, int N, int NPr,
                               uint16_t* __restrict__ wh, uint16_t* __restrict__ wl) {
    int i = blockIdx.x * blockDim.x + threadIdx.x;
    if (i >= NPr * K) return;
    int n = i / K, k = i % K;
    float v = (n < N) ? W[(size_t)k * N + n] : 0.f;
    __nv_bfloat16 h = __float2bfloat16(v);
    float res = v - __bfloat162float(h);
    __nv_bfloat16 l = __float2bfloat16(res);
    wh[i] = __nv_bfloat16_raw(h).x;
    wl[i] = __nv_bfloat16_raw(l).x;
}

// ================= mma.sync / cp.async helpers =================
__device__ __forceinline__ uint32_t smem_u32(const void* p) {
    uint32_t a;
    asm("{ .reg .u64 t; cvta.to.shared.u64 t, %1; cvt.u32.u64 %0, t; }" : "=r"(a) : "l"(p));
    return a;
}
__device__ __forceinline__ void ldsm_x4(uint32_t* r, uint32_t addr) {
    asm volatile("ldmatrix.sync.aligned.m8n8.x4.shared.b16 {%0,%1,%2,%3}, [%4];"
                 : "=r"(r[0]), "=r"(r[1]), "=r"(r[2]), "=r"(r[3]) : "r"(addr));
}
__device__ __forceinline__ void ldsm_x2(uint32_t* r, uint32_t addr) {
    asm volatile("ldmatrix.sync.aligned.m8n8.x2.shared.b16 {%0,%1}, [%2];"
                 : "=r"(r[0]), "=r"(r[1]) : "r"(addr));
}
__device__ __forceinline__ void mma_bf16(float* c, const uint32_t* a, const uint32_t* b) {
    asm volatile(
        "mma.sync.aligned.m16n8k16.row.col.f32.bf16.bf16.f32 "
        "{%0,%1,%2,%3}, {%4,%5,%6,%7}, {%8,%9}, {%0,%1,%2,%3};"
        : "+f"(c[0]), "+f"(c[1]), "+f"(c[2]), "+f"(c[3])
        : "r"(a[0]), "r"(a[1]), "r"(a[2]), "r"(a[3]), "r"(b[0]), "r"(b[1]));
}
__device__ __forceinline__ void cp16(uint32_t saddr, const void* gptr) {
    asm volatile("cp.async.cg.shared.global [%0], [%1], 16;" :: "r"(saddr), "l"(gptr));
}
__device__ __forceinline__ void cp_commit() { asm volatile("cp.async.commit_group;"); }
template <int N>
__device__ __forceinline__ void cp_wait() { asm volatile("cp.async.wait_group %0;" :: "n"(N)); }

#define G_STAGE 49152
#define G_OFF_AH 0
#define G_OFF_AL 16384
#define G_OFF_BH 32768
#define G_OFF_BL 40960

// shared compute step for one 64-K chunk (both GEMM kernels)
#define GEMM_COMPUTE(stb)                                                                  \
    do {                                                                                   \
        _Pragma("unroll")                                                                  \
        for (int ks = 0; ks < 4; ++ks) {                                                   \
            uint32_t ah[4][4], al[4][4], bh[2][2], bl[2][2];                               \
            _Pragma("unroll")                                                              \
            for (int mf = 0; mf < 4; ++mf) {                                               \
                int r = wm + mf * 16 + a_row_l;                                            \
                uint32_t so = r * 128 + (((ks * 2 + a_chl) ^ (r & 7)) << 4);               \
                ldsm_x4(ah[mf], (stb) + G_OFF_AH + so);                                    \
                ldsm_x4(al[mf], (stb) + G_OFF_AL + so);                                    \
            }                                                                              \
            _Pragma("unroll")                                                              \
            for (int nf = 0; nf < 2; ++nf) {                                               \
                int r = wn + nf * 8 + b_row_l;                                             \
                uint32_t so = r * 128 + (((ks * 2 + b_chl) ^ (r & 7)) << 4);               \
                ldsm_x2(bh[nf], (stb) + G_OFF_BH + so);                                    \
                ldsm_x2(bl[nf], (stb) + G_OFF_BL + so);                                    \
            }                                                                              \
            _Pragma("unroll")                                                              \
            for (int mf = 0; mf < 4; ++mf)                                                 \
                _Pragma("unroll")                                                          \
                for (int nf = 0; nf < 2; ++nf) {                                           \
                    mma_bf16(acc[mf][nf], ah[mf], bh[nf]);                                 \
                    mma_bf16(acc[mf][nf], ah[mf], bl[nf]);                                 \
                    mma_bf16(acc[mf][nf], al[mf], bh[nf]);                                 \
                }                                                                          \
        }                                                                                  \
    } while (0)

#define GEMM_EPILOGUE(NOUT)                                                                \
    do {                                                                                   \
        const int gid = lane >> 2, tid4 = lane & 3;                                        \
        _Pragma("unroll")                                                                  \
        for (int mf = 0; mf < 4; ++mf) {                                                   \
            _Pragma("unroll")                                                              \
            for (int nf = 0; nf < 2; ++nf) {                                               \
                int col = nb0 + wn + nf * 8 + tid4 * 2;                                    \
                if (col < (NOUT)) {                                                        \
                    int m0 = row0 + wm + mf * 16 + gid;                                    \
                    __half2 h0 = __floats2half2_rn(acc[mf][nf][0], acc[mf][nf][1]);        \
                    __half2 h1 = __floats2half2_rn(acc[mf][nf][2], acc[mf][nf][3]);        \
                    *(__half2*)(sup + (size_t)m0 * (NOUT) + col) = h0;                     \
                    *(__half2*)(sup + (size_t)(m0 + 8) * (NOUT) + col) = h1;               \
                }                                                                          \
            }                                                                              \
        }                                                                                  \
    } while (0)

// ================= generic HMMA GEMM (layers 2-4, pre-split bf16 A) =================
__global__ __launch_bounds__(256)
void gemm_hmma_kernel(const uint16_t* __restrict__ Ah, const uint16_t* __restrict__ Al,
                      const uint16_t* __restrict__ Bh, const uint16_t* __restrict__ Bl,
                      __half* __restrict__ sup, int K, int NOUT) {
    extern __shared__ __align__(128) char smem[];
    const uint32_t sb = smem_u32(smem);
    const int tid = threadIdx.x, wid = tid >> 5, lane = tid & 31;
    const int row0 = blockIdx.y * 128;
    const int nb0 = blockIdx.x * 64;
    const int wm = (wid & 1) * 64;
    const int wn = (wid >> 1) * 16;

    float acc[4][2][4];
#pragma unroll
    for (int i = 0; i < 4; i++)
#pragma unroll
        for (int j = 0; j < 2; j++)
#pragma unroll
            for (int q = 0; q < 4; q++) acc[i][j][q] = 0.f;

    const int a_row_l = lane & 15;
    const int a_chl = lane >> 4;
    const int b_row_l = lane & 7;
    const int b_chl = (lane >> 3) & 1;
    const int CH = K >> 6;

    auto load_stage = [&](int c, int buf) {
        const int kbase = c * 64;
        const uint32_t so_base = sb + buf * G_STAGE;
#pragma unroll
        for (int i = tid; i < 1024; i += 256) {
            int r = i >> 3, cb = i & 7;
            size_t gidx = (size_t)(row0 + r) * K + kbase + cb * 8;
            uint32_t so = r * 128 + ((cb ^ (r & 7)) << 4);
            cp16(so_base + G_OFF_AH + so, Ah + gidx);
            cp16(so_base + G_OFF_AL + so, Al + gidx);
        }
#pragma unroll
        for (int i = tid; i < 512; i += 256) {
            int r = i >> 3, cb = i & 7;
            size_t gidx = (size_t)(nb0 + r) * K + kbase + cb * 8;
            uint32_t so = r * 128 + ((cb ^ (r & 7)) << 4);
            cp16(so_base + G_OFF_BH + so, Bh + gidx);
            cp16(so_base + G_OFF_BL + so, Bl + gidx);
        }
        cp_commit();
    };

    load_stage(0, 0);
    for (int c = 0; c < CH; ++c) {
        if (c + 1 < CH) { load_stage(c + 1, (c + 1) & 1); cp_wait<1>(); }
        else cp_wait<0>();
        __syncthreads();
        const uint32_t stb = sb + (c & 1) * G_STAGE;
        GEMM_COMPUTE(stb);
        __syncthreads();
    }
    GEMM_EPILOGUE(NOUT);
}

// ================= layer-1 GEMM: fused fp32->bf16 hi/lo split of x =================
// A from x fp32 [NN x 512] (zero-padded rows >= NN), reg-staged double buffer.
__global__ __launch_bounds__(256)
void gemm_l1_kernel(const float* __restrict__ x,
                    const uint16_t* __restrict__ Bh, const uint16_t* __restrict__ Bl,
                    __half* __restrict__ sup) {
    extern __shared__ __align__(128) char smem[];
    const uint32_t sb = smem_u32(smem);
    const int tid = threadIdx.x, wid = tid >> 5, lane = tid & 31;
    const int row0 = blockIdx.y * 128;
    const int nb0 = blockIdx.x * 64;
    const int wm = (wid & 1) * 64;
    const int wn = (wid >> 1) * 16;
    const int K = 512, NOUT = 256, CH = 8;

    float acc[4][2][4];
#pragma unroll
    for (int i = 0; i < 4; i++)
#pragma unroll
        for (int j = 0; j < 2; j++)
#pragma unroll
            for (int q = 0; q < 4; q++) acc[i][j][q] = 0.f;

    const int a_row_l = lane & 15;
    const int a_chl = lane >> 4;
    const int b_row_l = lane & 7;
    const int b_chl = (lane >> 3) & 1;

    float4 areg[4][2];  // 4 iters x 8 floats staged per thread

    auto load_a = [&](int c) {
        const int kbase = c * 64;
#pragma unroll
        for (int it = 0; it < 4; it++) {
            int i = tid + it * 256;
            int r = i >> 3, cb = i & 7;
            int grow = row0 + r;
            if (grow < NN) {
                const float* gp = x + (size_t)grow * K + kbase + cb * 8;
                areg[it][0] = *(const float4*)gp;
                areg[it][1] = *(const float4*)(gp + 4);
            } else {
                areg[it][0] = make_float4(0.f, 0.f, 0.f, 0.f);
                areg[it][1] = make_float4(0.f, 0.f, 0.f, 0.f);
            }
        }
    };
    auto store_a = [&](int buf) {
        const uint32_t so_base = sb + buf * G_STAGE;
#pragma unroll
        for (int it = 0; it < 4; it++) {
            int i = tid + it * 256;
            int r = i >> 3, cb = i & 7;
            uint32_t so = r * 128 + ((cb ^ (r & 7)) << 4);
            float f[8] = {areg[it][0].x, areg[it][0].y, areg[it][0].z, areg[it][0].w,
                          areg[it][1].x, areg[it][1].y, areg[it][1].z, areg[it][1].w};
            uint32_t hi[4], lo[4];
#pragma unroll
            for (int q = 0; q < 4; q++) split2(f[2 * q], f[2 * q + 1], hi[q], lo[q]);
            *(uint4*)(smem + buf * G_STAGE + G_OFF_AH + so) = make_uint4(hi[0], hi[1], hi[2], hi[3]);
            *(uint4*)(smem + buf * G_STAGE + G_OFF_AL + so) = make_uint4(lo[0], lo[1], lo[2], lo[3]);
        }
        (void)so_base;
    };
    auto load_b = [&](int c, int buf) {
        const int kbase = c * 64;
        const uint32_t so_base = sb + buf * G_STAGE;
#pragma unroll
        for (int i = tid; i < 512; i += 256) {
            int r = i >> 3, cb = i & 7;
            size_t gidx = (size_t)(nb0 + r) * K + kbase + cb * 8;
            uint32_t so = r * 128 + ((cb ^ (r & 7)) << 4);
            cp16(so_base + G_OFF_BH + so, Bh + gidx);
            cp16(so_base + G_OFF_BL + so, Bl + gidx);
        }
        cp_commit();
    };

    // prologue: stage 0
    load_a(0);
    load_b(0, 0);
    store_a(0);
    cp_wait<0>();
    __syncthreads();

    for (int c = 0; c < CH; ++c) {
        if (c + 1 < CH) { load_a(c + 1); load_b(c + 1, (c + 1) & 1); }
        const uint32_t stb = sb + (c & 1) * G_STAGE;
        GEMM_COMPUTE(stb);
        if (c + 1 < CH) {
            store_a((c + 1) & 1);   // writes the other buffer; stage c-1 readers done (sync below from prev iter)
            cp_wait<0>();
            __syncthreads();
        }
    }
    GEMM_EPILOGUE(NOUT);
}

// ================= SpMM gather (fp16 support, 16B/lane, x4 edge unroll) ============
template <int D>
__global__ void spmm_vec_kernel(const __half* __restrict__ sup, const float* __restrict__ bias,
                                uint16_t* __restrict__ act_hi, uint16_t* __restrict__ act_lo) {
    constexpr int LPE = D / 8;
    constexpr int EPI = 32 / LPE;
    const int warp = (blockIdx.x * blockDim.x + threadIdx.x) >> 5;
    const int lane = threadIdx.x & 31;
    if (warp >= NN) return;
    const int sub = lane / LPE;
    const int seg = lane % LPE;

    float acc[8];
#pragma unroll
    for (int q = 0; q < 8; q++) acc[q] = 0.f;

    const int e0 = g_rowptr[warp];
    const int e1 = g_rowptr[warp + 1];
    int e = e0;
    for (; e + 4 * EPI <= e1; e += 4 * EPI) {
        int s[4]; float w[4]; uint4 v[4];
#pragma unroll
        for (int u = 0; u < 4; u++) {
            int me = e + u * EPI + sub;
            s[u] = g_esrc[me];
            w[u] = g_ew[me];
        }
#pragma unroll
        for (int u = 0; u < 4; u++)
            v[u] = *((const uint4*)(sup + (size_t)s[u] * D) + seg);
#pragma unroll
        for (int u = 0; u < 4; u++) {
            float2 f0 = __half22float2(*(__half2*)&v[u].x);
            float2 f1 = __half22float2(*(__half2*)&v[u].y);
            float2 f2 = __half22float2(*(__half2*)&v[u].z);
            float2 f3 = __half22float2(*(__half2*)&v[u].w);
            acc[0] += w[u] * f0.x; acc[1] += w[u] * f0.y;
            acc[2] += w[u] * f1.x; acc[3] += w[u] * f1.y;
            acc[4] += w[u] * f2.x; acc[5] += w[u] * f2.y;
            acc[6] += w[u] * f3.x; acc[7] += w[u] * f3.y;
        }
    }
    for (; e < e1; e += EPI) {
        int me = e + sub;
        if (me < e1) {
            int s = g_esrc[me];
            float w = g_ew[me];
            uint4 v = *((const uint4*)(sup + (size_t)s * D) + seg);
            float2 f0 = __half22float2(*(__half2*)&v.x);
            float2 f1 = __half22float2(*(__half2*)&v.y);
            float2 f2 = __half22float2(*(__half2*)&v.z);
            float2 f3 = __half22float2(*(__half2*)&v.w);
            acc[0] += w * f0.x; acc[1] += w * f0.y;
            acc[2] += w * f1.x; acc[3] += w * f1.y;
            acc[4] += w * f2.x; acc[5] += w * f2.y;
            acc[6] += w * f3.x; acc[7] += w * f3.y;
        }
    }
#pragma unroll
    for (int off = LPE; off < 32; off <<= 1)
#pragma unroll
        for (int q = 0; q < 8; q++)
            acc[q] += __shfl_xor_sync(0xFFFFFFFFu, acc[q], off);

    if (lane < LPE) {
        int col0 = lane * 8;
        uint32_t hh[4], ll[4];
#pragma unroll
        for (int q = 0; q < 8; q += 2) {
            float vx = fmaxf(acc[q] + bias[col0 + q], 0.f);
            float vy = fmaxf(acc[q + 1] + bias[col0 + q + 1], 0.f);
            split2(vx, vy, hh[q >> 1], ll[q >> 1]);
        }
        *(uint4*)(act_hi + (size_t)warp * D + col0) = make_uint4(hh[0], hh[1], hh[2], hh[3]);
        *(uint4*)(act_lo + (size_t)warp * D + col0) = make_uint4(ll[0], ll[1], ll[2], ll[3]);
    }
}

// ======== last layer: SpMM (D=40) fused with relu + log-softmax -> d_out =========
__global__ void spmm_lsm_kernel(const __half* __restrict__ sup, const float* __restrict__ bias,
                                float* __restrict__ out) {
    const int warp = (blockIdx.x * blockDim.x + threadIdx.x) >> 5;
    const int lane = threadIdx.x & 31;
    if (warp >= NN) return;
    float ax = 0.f, ay = 0.f;
    const int e0 = g_rowptr[warp];
    const int e1 = g_rowptr[warp + 1];
    const bool act = lane < 20;
    int e = e0;
    for (; e + 4 <= e1; e += 4) {
        int s[4]; float w[4]; float2 f[4];
#pragma unroll
        for (int u = 0; u < 4; u++) { s[u] = g_esrc[e + u]; w[u] = g_ew[e + u]; }
#pragma unroll
        for (int u = 0; u < 4; u++)
            f[u] = act ? __half22float2(((const __half2*)(sup + (size_t)s[u] * 40))[lane])
                       : make_float2(0.f, 0.f);
#pragma unroll
        for (int u = 0; u < 4; u++) { ax += w[u] * f[u].x; ay += w[u] * f[u].y; }
    }
    for (; e < e1; e++) {
        int s = g_esrc[e];
        float w = g_ew[e];
        if (act) {
            float2 f = __half22float2(((const __half2*)(sup + (size_t)s * 40))[lane]);
            ax += w * f.x; ay += w * f.y;
        }
    }
    float vx = act ? fmaxf(ax + bias[2 * lane], 0.f) : -INFINITY;
    float vy = act ? fmaxf(ay + bias[2 * lane + 1], 0.f) : -INFINITY;
    float m = fmaxf(vx, vy);
#pragma unroll
    for (int off = 16; off > 0; off >>= 1)
        m = fmaxf(m, __shfl_xor_sync(0xFFFFFFFFu, m, off));
    float s = act ? (expf(vx - m) + expf(vy - m)) : 0.f;
#pragma unroll
    for (int off = 16; off > 0; off >>= 1)
        s += __shfl_xor_sync(0xFFFFFFFFu, s, off);
    float lse = logf(s) + m;
    if (act) {
        out[(size_t)warp * 40 + 2 * lane] = vx - lse;
        out[(size_t)warp * 40 + 2 * lane + 1] = vy - lse;
    }
}

// ================= launch =================
extern "C" void kernel_launch(void* const* d_in, const int* in_sizes, int n_in,
                              void* d_out, int out_size) {
    const float* x  = (const float*)d_in[0];
    const int* esrc = (const int*)d_in[1];
    const int* edst = (const int*)d_in[2];
    const float* ew = (const float*)d_in[3];
    const float* W1 = (const float*)d_in[4];
    const float* b1 = (const float*)d_in[5];
    const float* W2 = (const float*)d_in[6];
    const float* b2 = (const float*)d_in[7];
    const float* W3 = (const float*)d_in[8];
    const float* b3 = (const float*)d_in[9];
    const float* W4 = (const float*)d_in[10];
    const float* b4 = (const float*)d_in[11];
    float* out = (float*)d_out;

    uint16_t *ah, *al, *suph_u, *wh, *wl;
    cudaGetSymbolAddress((void**)&ah, g_a_hi);
    cudaGetSymbolAddress((void**)&al, g_a_lo);
    cudaGetSymbolAddress((void**)&suph_u, g_suph);
    cudaGetSymbolAddress((void**)&wh, g_wh);
    cudaGetSymbolAddress((void**)&wl, g_wl);
    __half* suph = (__half*)suph_u;

    const int WOFF1 = 0, WOFF2 = 131072, WOFF3 = 163840, WOFF4 = 172032;

    const int GSMEM = 2 * G_STAGE;  // 96KB, 2-stage
    cudaFuncSetAttribute(gemm_hmma_kernel, cudaFuncAttributeMaxDynamicSharedMemorySize, GSMEM);
    cudaFuncSetAttribute(gemm_l1_kernel, cudaFuncAttributeMaxDynamicSharedMemorySize, GSMEM);

    static cudaStream_t s2 = nullptr;
    static cudaEvent_t ev_fork = nullptr, ev_join = nullptr;
    if (!s2) {
        cudaStreamCreateWithFlags(&s2, cudaStreamNonBlocking);
        cudaEventCreateWithFlags(&ev_fork, cudaEventDisableTiming);
        cudaEventCreateWithFlags(&ev_join, cudaEventDisableTiming);
    }

    cudaEventRecord(ev_fork, 0);
    cudaStreamWaitEvent(s2, ev_fork, 0);
    zero_counts_kernel<<<(NN + 255) / 256, 256, 0, s2>>>();
    hist_kernel<<<(NE + 255) / 256, 256, 0, s2>>>(edst);
    scan_kernel<<<1, 1024, 0, s2>>>();
    scatter_kernel<<<(NE + 255) / 256, 256, 0, s2>>>(esrc, edst, ew);
    cudaEventRecord(ev_join, s2);

    // weight splits (tiny) on main stream
    split_w_kernel<<<(256 * 512 + 255) / 256, 256>>>(W1, 512, 256, 256, wh + WOFF1, wl + WOFF1);
    split_w_kernel<<<(128 * 256 + 255) / 256, 256>>>(W2, 256, 128, 128, wh + WOFF2, wl + WOFF2);
    split_w_kernel<<<(64 * 128 + 255) / 256, 256>>>(W3, 128, 64, 64, wh + WOFF3, wl + WOFF3);
    split_w_kernel<<<(64 * 64 + 255) / 256, 256>>>(W4, 64, 40, 64, wh + WOFF4, wl + WOFF4);

    const int GY = MP / 128;  // 782
    const int SPMM_BLOCKS = (NN * 32 + 255) / 256;

    // Layer 1 (fused split): 512 -> 256
    gemm_l1_kernel<<<dim3(4, GY), 256, GSMEM>>>(x, wh + WOFF1, wl + WOFF1, suph);
    cudaStreamWaitEvent(0, ev_join, 0);
    spmm_vec_kernel<256><<<SPMM_BLOCKS, 256>>>(suph, b1, ah, al);

    gemm_hmma_kernel<<<dim3(2, GY), 256, GSMEM>>>(ah, al, wh + WOFF2, wl + WOFF2, suph, 256, 128);
    spmm_vec_kernel<128><<<SPMM_BLOCKS, 256>>>(suph, b2, ah, al);

    gemm_hmma_kernel<<<dim3(1, GY), 256, GSMEM>>>(ah, al, wh + WOFF3, wl + WOFF3, suph, 128, 64);
    spmm_vec_kernel<64><<<SPMM_BLOCKS, 256>>>(suph, b3, ah, al);

    gemm_hmma_kernel<<<dim3(1, GY), 256, GSMEM>>>(ah, al, wh + WOFF4, wl + WOFF4, suph, 64, 40);
    spmm_lsm_kernel<<<SPMM_BLOCKS, 256>>>(suph, b4, out);
}

// round 10
// speedup vs baseline: 3.0274x; 1.0517x over previous
#include <cuda_runtime.h>
#include <cuda_fp16.h>
#include <cuda_bf16.h>
#include <cstdint>

#define NN 100000
#define NE 3200000
#define MP 100096   // 782 * 128 (padded rows)

// ================= scratch =================
__device__ uint16_t g_a_hi[(size_t)MP * 512];   // fp16 activations (hi)
__device__ uint16_t g_a_lo[(size_t)MP * 512];   // fp16 activations (lo)
__device__ uint16_t g_suph[(size_t)MP * 256];   // fp16 support (GEMM out)
__device__ uint16_t g_wh[180224];               // fp16 Wt (all layers)
__device__ int   g_rowptr[NN + 1];
__device__ int   g_cursor[NN];
__device__ int   g_esrc[NE];
__device__ float g_ew[NE];

// ================= CSR build =================
__global__ void zero_counts_kernel() {
    int i = blockIdx.x * blockDim.x + threadIdx.x;
    if (i < NN) g_cursor[i] = 0;
}
__global__ void hist_kernel(const int* __restrict__ dst) {
    int e = blockIdx.x * blockDim.x + threadIdx.x;
    if (e < NE) atomicAdd(&g_cursor[dst[e]], 1);
}
__global__ void scan_kernel() {
    __shared__ int sdata[1024];
    const int T = 1024;
    const int CH = (NN + T - 1) / T;
    int t = threadIdx.x;
    int base = t * CH;
    int s = 0;
    for (int i = 0; i < CH; i++) { int idx = base + i; if (idx < NN) s += g_cursor[idx]; }
    sdata[t] = s;
    __syncthreads();
    for (int off = 1; off < T; off <<= 1) {
        int v = (t >= off) ? sdata[t - off] : 0;
        __syncthreads(); sdata[t] += v; __syncthreads();
    }
    int running = sdata[t] - s;
    for (int i = 0; i < CH; i++) {
        int idx = base + i;
        if (idx < NN) {
            int c = g_cursor[idx];
            g_rowptr[idx] = running;
            g_cursor[idx] = running;
            running += c;
        }
    }
    if (t == 0) g_rowptr[NN] = NE;
}
__global__ void scatter_kernel(const int* __restrict__ src, const int* __restrict__ dst,
                               const float* __restrict__ ew) {
    int e = blockIdx.x * blockDim.x + threadIdx.x;
    if (e < NE) {
        int d = dst[e];
        int pos = atomicAdd(&g_cursor[d], 1);
        g_esrc[pos] = src[e];
        g_ew[pos] = ew[e];
    }
}

// ================= fp16 hi/lo split helper =================
__device__ __forceinline__ void split2h(float f0, float f1, uint32_t& hi, uint32_t& lo) {
    __half h0 = __float2half_rn(f0), h1 = __float2half_rn(f1);
    float r0 = f0 - __half2float(h0), r1 = f1 - __half2float(h1);
    __half l0 = __float2half_rn(r0), l1 = __float2half_rn(r1);
    hi = (uint32_t)__half_raw(h0).x | ((uint32_t)__half_raw(h1).x << 16);
    lo = (uint32_t)__half_raw(l0).x | ((uint32_t)__half_raw(l1).x << 16);
}

// ===== combined weight transpose+convert: W[K,N] fp32 -> Wt[NPr,K] fp16, all 4 layers =====
__global__ void split_w_all(const float* __restrict__ W1, const float* __restrict__ W2,
                            const float* __restrict__ W3, const float* __restrict__ W4) {
    int i = blockIdx.x * blockDim.x + threadIdx.x;
    if (i >= 176128) return;
    const float* W; int K, N, off;
    if (i < 131072)      { W = W1; K = 512; N = 256; off = 0; }
    else if (i < 163840) { W = W2; K = 256; N = 128; off = 131072; }
    else if (i < 172032) { W = W3; K = 128; N = 64;  off = 163840; }
    else                 { W = W4; K = 64;  N = 40;  off = 172032; }
    int local = i - off;
    int n = local / K, k = local % K;
    float v = (n < N) ? W[(size_t)k * N + n] : 0.f;
    g_wh[i] = __half_raw(__float2half_rn(v)).x;
}

// ================= mma.sync / cp.async helpers =================
__device__ __forceinline__ uint32_t smem_u32(const void* p) {
    uint32_t a;
    asm("{ .reg .u64 t; cvta.to.shared.u64 t, %1; cvt.u32.u64 %0, t; }" : "=r"(a) : "l"(p));
    return a;
}
__device__ __forceinline__ void ldsm_x4(uint32_t* r, uint32_t addr) {
    asm volatile("ldmatrix.sync.aligned.m8n8.x4.shared.b16 {%0,%1,%2,%3}, [%4];"
                 : "=r"(r[0]), "=r"(r[1]), "=r"(r[2]), "=r"(r[3]) : "r"(addr));
}
__device__ __forceinline__ void ldsm_x2(uint32_t* r, uint32_t addr) {
    asm volatile("ldmatrix.sync.aligned.m8n8.x2.shared.b16 {%0,%1}, [%2];"
                 : "=r"(r[0]), "=r"(r[1]) : "r"(addr));
}
__device__ __forceinline__ void mma_f16(float* c, const uint32_t* a, const uint32_t* b) {
    asm volatile(
        "mma.sync.aligned.m16n8k16.row.col.f32.f16.f16.f32 "
        "{%0,%1,%2,%3}, {%4,%5,%6,%7}, {%8,%9}, {%0,%1,%2,%3};"
        : "+f"(c[0]), "+f"(c[1]), "+f"(c[2]), "+f"(c[3])
        : "r"(a[0]), "r"(a[1]), "r"(a[2]), "r"(a[3]), "r"(b[0]), "r"(b[1]));
}
__device__ __forceinline__ void cp16(uint32_t saddr, const void* gptr) {
    asm volatile("cp.async.cg.shared.global [%0], [%1], 16;" :: "r"(saddr), "l"(gptr));
}
__device__ __forceinline__ void cp_commit() { asm volatile("cp.async.commit_group;"); }
template <int N>
__device__ __forceinline__ void cp_wait() { asm volatile("cp.async.wait_group %0;" :: "n"(N)); }

#define G_STAGE 40960
#define G_OFF_AH 0
#define G_OFF_AL 16384
#define G_OFF_BH 32768

// one 64-K chunk compute (2-term fp16 split: ah*wh + al*wh)
#define GEMM_COMPUTE(stb)                                                                  \
    do {                                                                                   \
        _Pragma("unroll")                                                                  \
        for (int ks = 0; ks < 4; ++ks) {                                                   \
            uint32_t ah[4][4], al[4][4], bh[2][2];                                         \
            _Pragma("unroll")                                                              \
            for (int mf = 0; mf < 4; ++mf) {                                               \
                int r = wm + mf * 16 + a_row_l;                                            \
                uint32_t so = r * 128 + (((ks * 2 + a_chl) ^ (r & 7)) << 4);               \
                ldsm_x4(ah[mf], (stb) + G_OFF_AH + so);                                    \
                ldsm_x4(al[mf], (stb) + G_OFF_AL + so);                                    \
            }                                                                              \
            _Pragma("unroll")                                                              \
            for (int nf = 0; nf < 2; ++nf) {                                               \
                int r = wn + nf * 8 + b_row_l;                                             \
                uint32_t so = r * 128 + (((ks * 2 + b_chl) ^ (r & 7)) << 4);               \
                ldsm_x2(bh[nf], (stb) + G_OFF_BH + so);                                    \
            }                                                                              \
            _Pragma("unroll")                                                              \
            for (int mf = 0; mf < 4; ++mf)                                                 \
                _Pragma("unroll")                                                          \
                for (int nf = 0; nf < 2; ++nf) {                                           \
                    mma_f16(acc[mf][nf], ah[mf], bh[nf]);                                  \
                    mma_f16(acc[mf][nf], al[mf], bh[nf]);                                  \
                }                                                                          \
        }                                                                                  \
    } while (0)

#define GEMM_EPILOGUE(NOUT)                                                                \
    do {                                                                                   \
        const int gid = lane >> 2, tid4 = lane & 3;                                        \
        _Pragma("unroll")                                                                  \
        for (int mf = 0; mf < 4; ++mf) {                                                   \
            _Pragma("unroll")                                                              \
            for (int nf = 0; nf < 2; ++nf) {                                               \
                int col = nb0 + wn + nf * 8 + tid4 * 2;                                    \
                if (col < (NOUT)) {                                                        \
                    int m0 = row0 + wm + mf * 16 + gid;                                    \
                    __half2 h0 = __floats2half2_rn(acc[mf][nf][0], acc[mf][nf][1]);        \
                    __half2 h1 = __floats2half2_rn(acc[mf][nf][2], acc[mf][nf][3]);        \
                    *(__half2*)(sup + (size_t)m0 * (NOUT) + col) = h0;                     \
                    *(__half2*)(sup + (size_t)(m0 + 8) * (NOUT) + col) = h1;               \
                }                                                                          \
            }                                                                              \
        }                                                                                  \
    } while (0)

// ================= generic HMMA GEMM (layers 2-4, pre-split fp16 A) =================
__global__ __launch_bounds__(256)
void gemm_hmma_kernel(const uint16_t* __restrict__ Ah, const uint16_t* __restrict__ Al,
                      const uint16_t* __restrict__ Bh,
                      __half* __restrict__ sup, int K, int NOUT) {
    extern __shared__ __align__(128) char smem[];
    const uint32_t sb = smem_u32(smem);
    const int tid = threadIdx.x, wid = tid >> 5, lane = tid & 31;
    const int row0 = blockIdx.y * 128;
    const int nb0 = blockIdx.x * 64;
    const int wm = (wid & 1) * 64;
    const int wn = (wid >> 1) * 16;

    float acc[4][2][4];
#pragma unroll
    for (int i = 0; i < 4; i++)
#pragma unroll
        for (int j = 0; j < 2; j++)
#pragma unroll
            for (int q = 0; q < 4; q++) acc[i][j][q] = 0.f;

    const int a_row_l = lane & 15;
    const int a_chl = lane >> 4;
    const int b_row_l = lane & 7;
    const int b_chl = (lane >> 3) & 1;
    const int CH = K >> 6;

    auto load_stage = [&](int c, int buf) {
        const int kbase = c * 64;
        const uint32_t so_base = sb + buf * G_STAGE;
#pragma unroll
        for (int i = tid; i < 1024; i += 256) {
            int r = i >> 3, cb = i & 7;
            size_t gidx = (size_t)(row0 + r) * K + kbase + cb * 8;
            uint32_t so = r * 128 + ((cb ^ (r & 7)) << 4);
            cp16(so_base + G_OFF_AH + so, Ah + gidx);
            cp16(so_base + G_OFF_AL + so, Al + gidx);
        }
#pragma unroll
        for (int i = tid; i < 512; i += 256) {
            int r = i >> 3, cb = i & 7;
            size_t gidx = (size_t)(nb0 + r) * K + kbase + cb * 8;
            uint32_t so = r * 128 + ((cb ^ (r & 7)) << 4);
            cp16(so_base + G_OFF_BH + so, Bh + gidx);
        }
        cp_commit();
    };

    load_stage(0, 0);
    for (int c = 0; c < CH; ++c) {
        if (c + 1 < CH) { load_stage(c + 1, (c + 1) & 1); cp_wait<1>(); }
        else cp_wait<0>();
        __syncthreads();
        const uint32_t stb = sb + (c & 1) * G_STAGE;
        GEMM_COMPUTE(stb);
        __syncthreads();
    }
    GEMM_EPILOGUE(NOUT);
}

// ================= layer-1 GEMM: fused fp32->fp16 hi/lo split of x =================
__global__ __launch_bounds__(256)
void gemm_l1_kernel(const float* __restrict__ x,
                    const uint16_t* __restrict__ Bh,
                    __half* __restrict__ sup) {
    extern __shared__ __align__(128) char smem[];
    const uint32_t sb = smem_u32(smem);
    const int tid = threadIdx.x, wid = tid >> 5, lane = tid & 31;
    const int row0 = blockIdx.y * 128;
    const int nb0 = blockIdx.x * 64;
    const int wm = (wid & 1) * 64;
    const int wn = (wid >> 1) * 16;
    const int K = 512, NOUT = 256, CH = 8;

    float acc[4][2][4];
#pragma unroll
    for (int i = 0; i < 4; i++)
#pragma unroll
        for (int j = 0; j < 2; j++)
#pragma unroll
            for (int q = 0; q < 4; q++) acc[i][j][q] = 0.f;

    const int a_row_l = lane & 15;
    const int a_chl = lane >> 4;
    const int b_row_l = lane & 7;
    const int b_chl = (lane >> 3) & 1;

    float4 areg[4][2];

    auto load_a = [&](int c) {
        const int kbase = c * 64;
#pragma unroll
        for (int it = 0; it < 4; it++) {
            int i = tid + it * 256;
            int r = i >> 3, cb = i & 7;
            int grow = row0 + r;
            if (grow < NN) {
                const float* gp = x + (size_t)grow * K + kbase + cb * 8;
                areg[it][0] = *(const float4*)gp;
                areg[it][1] = *(const float4*)(gp + 4);
            } else {
                areg[it][0] = make_float4(0.f, 0.f, 0.f, 0.f);
                areg[it][1] = make_float4(0.f, 0.f, 0.f, 0.f);
            }
        }
    };
    auto store_a = [&](int buf) {
#pragma unroll
        for (int it = 0; it < 4; it++) {
            int i = tid + it * 256;
            int r = i >> 3, cb = i & 7;
            uint32_t so = r * 128 + ((cb ^ (r & 7)) << 4);
            float f[8] = {areg[it][0].x, areg[it][0].y, areg[it][0].z, areg[it][0].w,
                          areg[it][1].x, areg[it][1].y, areg[it][1].z, areg[it][1].w};
            uint32_t hi[4], lo[4];
#pragma unroll
            for (int q = 0; q < 4; q++) split2h(f[2 * q], f[2 * q + 1], hi[q], lo[q]);
            *(uint4*)(smem + buf * G_STAGE + G_OFF_AH + so) = make_uint4(hi[0], hi[1], hi[2], hi[3]);
            *(uint4*)(smem + buf * G_STAGE + G_OFF_AL + so) = make_uint4(lo[0], lo[1], lo[2], lo[3]);
        }
    };
    auto load_b = [&](int c, int buf) {
        const int kbase = c * 64;
        const uint32_t so_base = sb + buf * G_STAGE;
#pragma unroll
        for (int i = tid; i < 512; i += 256) {
            int r = i >> 3, cb = i & 7;
            size_t gidx = (size_t)(nb0 + r) * K + kbase + cb * 8;
            uint32_t so = r * 128 + ((cb ^ (r & 7)) << 4);
            cp16(so_base + G_OFF_BH + so, Bh + gidx);
        }
        cp_commit();
    };

    load_a(0);
    load_b(0, 0);
    store_a(0);
    cp_wait<0>();
    __syncthreads();

    for (int c = 0; c < CH; ++c) {
        if (c + 1 < CH) { load_a(c + 1); load_b(c + 1, (c + 1) & 1); }
        const uint32_t stb = sb + (c & 1) * G_STAGE;
        GEMM_COMPUTE(stb);
        if (c + 1 < CH) {
            store_a((c + 1) & 1);
            cp_wait<0>();
            __syncthreads();
        }
    }
    GEMM_EPILOGUE(NOUT);
}

// ================= SpMM gather (fp16 support, 16B/lane, x4 edge unroll) ============
template <int D>
__global__ void spmm_vec_kernel(const __half* __restrict__ sup, const float* __restrict__ bias,
                                uint16_t* __restrict__ act_hi, uint16_t* __restrict__ act_lo) {
    constexpr int LPE = D / 8;
    constexpr int EPI = 32 / LPE;
    const int warp = (blockIdx.x * blockDim.x + threadIdx.x) >> 5;
    const int lane = threadIdx.x & 31;
    if (warp >= NN) return;
    const int sub = lane / LPE;
    const int seg = lane % LPE;

    float acc[8];
#pragma unroll
    for (int q = 0; q < 8; q++) acc[q] = 0.f;

    const int e0 = g_rowptr[warp];
    const int e1 = g_rowptr[warp + 1];
    int e = e0;
    for (; e + 4 * EPI <= e1; e += 4 * EPI) {
        int s[4]; float w[4]; uint4 v[4];
#pragma unroll
        for (int u = 0; u < 4; u++) {
            int me = e + u * EPI + sub;
            s[u] = g_esrc[me];
            w[u] = g_ew[me];
        }
#pragma unroll
        for (int u = 0; u < 4; u++)
            v[u] = *((const uint4*)(sup + (size_t)s[u] * D) + seg);
#pragma unroll
        for (int u = 0; u < 4; u++) {
            float2 f0 = __half22float2(*(__half2*)&v[u].x);
            float2 f1 = __half22float2(*(__half2*)&v[u].y);
            float2 f2 = __half22float2(*(__half2*)&v[u].z);
            float2 f3 = __half22float2(*(__half2*)&v[u].w);
            acc[0] += w[u] * f0.x; acc[1] += w[u] * f0.y;
            acc[2] += w[u] * f1.x; acc[3] += w[u] * f1.y;
            acc[4] += w[u] * f2.x; acc[5] += w[u] * f2.y;
            acc[6] += w[u] * f3.x; acc[7] += w[u] * f3.y;
        }
    }
    for (; e < e1; e += EPI) {
        int me = e + sub;
        if (me < e1) {
            int s = g_esrc[me];
            float w = g_ew[me];
            uint4 v = *((const uint4*)(sup + (size_t)s * D) + seg);
            float2 f0 = __half22float2(*(__half2*)&v.x);
            float2 f1 = __half22float2(*(__half2*)&v.y);
            float2 f2 = __half22float2(*(__half2*)&v.z);
            float2 f3 = __half22float2(*(__half2*)&v.w);
            acc[0] += w * f0.x; acc[1] += w * f0.y;
            acc[2] += w * f1.x; acc[3] += w * f1.y;
            acc[4] += w * f2.x; acc[5] += w * f2.y;
            acc[6] += w * f3.x; acc[7] += w * f3.y;
        }
    }
#pragma unroll
    for (int off = LPE; off < 32; off <<= 1)
#pragma unroll
        for (int q = 0; q < 8; q++)
            acc[q] += __shfl_xor_sync(0xFFFFFFFFu, acc[q], off);

    if (lane < LPE) {
        int col0 = lane * 8;
        uint32_t hh[4], ll[4];
#pragma unroll
        for (int q = 0; q < 8; q += 2) {
            float vx = fmaxf(acc[q] + bias[col0 + q], 0.f);
            float vy = fmaxf(acc[q + 1] + bias[col0 + q + 1], 0.f);
            split2h(vx, vy, hh[q >> 1], ll[q >> 1]);
        }
        *(uint4*)(act_hi + (size_t)warp * D + col0) = make_uint4(hh[0], hh[1], hh[2], hh[3]);
        *(uint4*)(act_lo + (size_t)warp * D + col0) = make_uint4(ll[0], ll[1], ll[2], ll[3]);
    }
}

// ======== last layer: SpMM (D=40) fused with relu + log-softmax -> d_out =========
__global__ void spmm_lsm_kernel(const __half* __restrict__ sup, const float* __restrict__ bias,
                                float* __restrict__ out) {
    const int warp = (blockIdx.x * blockDim.x + threadIdx.x) >> 5;
    const int lane = threadIdx.x & 31;
    if (warp >= NN) return;
    float ax = 0.f, ay = 0.f;
    const int e0 = g_rowptr[warp];
    const int e1 = g_rowptr[warp + 1];
    const bool act = lane < 20;
    int e = e0;
    for (; e + 4 <= e1; e += 4) {
        int s[4]; float w[4]; float2 f[4];
#pragma unroll
        for (int u = 0; u < 4; u++) { s[u] = g_esrc[e + u]; w[u] = g_ew[e + u]; }
#pragma unroll
        for (int u = 0; u < 4; u++)
            f[u] = act ? __half22float2(((const __half2*)(sup + (size_t)s[u] * 40))[lane])
                       : make_float2(0.f, 0.f);
#pragma unroll
        for (int u = 0; u < 4; u++) { ax += w[u] * f[u].x; ay += w[u] * f[u].y; }
    }
    for (; e < e1; e++) {
        int s = g_esrc[e];
        float w = g_ew[e];
        if (act) {
            float2 f = __half22float2(((const __half2*)(sup + (size_t)s * 40))[lane]);
            ax += w * f.x; ay += w * f.y;
        }
    }
    float vx = act ? fmaxf(ax + bias[2 * lane], 0.f) : -INFINITY;
    float vy = act ? fmaxf(ay + bias[2 * lane + 1], 0.f) : -INFINITY;
    float m = fmaxf(vx, vy);
#pragma unroll
    for (int off = 16; off > 0; off >>= 1)
        m = fmaxf(m, __shfl_xor_sync(0xFFFFFFFFu, m, off));
    float s = act ? (expf(vx - m) + expf(vy - m)) : 0.f;
#pragma unroll
    for (int off = 16; off > 0; off >>= 1)
        s += __shfl_xor_sync(0xFFFFFFFFu, s, off);
    float lse = logf(s) + m;
    if (act) {
        out[(size_t)warp * 40 + 2 * lane] = vx - lse;
        out[(size_t)warp * 40 + 2 * lane + 1] = vy - lse;
    }
}

// ================= launch =================
extern "C" void kernel_launch(void* const* d_in, const int* in_sizes, int n_in,
                              void* d_out, int out_size) {
    const float* x  = (const float*)d_in[0];
    const int* esrc = (const int*)d_in[1];
    const int* edst = (const int*)d_in[2];
    const float* ew = (const float*)d_in[3];
    const float* W1 = (const float*)d_in[4];
    const float* b1 = (const float*)d_in[5];
    const float* W2 = (const float*)d_in[6];
    const float* b2 = (const float*)d_in[7];
    const float* W3 = (const float*)d_in[8];
    const float* b3 = (const float*)d_in[9];
    const float* W4 = (const float*)d_in[10];
    const float* b4 = (const float*)d_in[11];
    float* out = (float*)d_out;

    uint16_t *ah, *al, *suph_u, *wh;
    cudaGetSymbolAddress((void**)&ah, g_a_hi);
    cudaGetSymbolAddress((void**)&al, g_a_lo);
    cudaGetSymbolAddress((void**)&suph_u, g_suph);
    cudaGetSymbolAddress((void**)&wh, g_wh);
    __half* suph = (__half*)suph_u;

    const int WOFF1 = 0, WOFF2 = 131072, WOFF3 = 163840, WOFF4 = 172032;

    const int GSMEM = 2 * G_STAGE;  // 80KB, 2-stage
    cudaFuncSetAttribute(gemm_hmma_kernel, cudaFuncAttributeMaxDynamicSharedMemorySize, GSMEM);
    cudaFuncSetAttribute(gemm_l1_kernel, cudaFuncAttributeMaxDynamicSharedMemorySize, GSMEM);

    static cudaStream_t s2 = nullptr;
    static cudaEvent_t ev_fork = nullptr, ev_join = nullptr;
    if (!s2) {
        cudaStreamCreateWithFlags(&s2, cudaStreamNonBlocking);
        cudaEventCreateWithFlags(&ev_fork, cudaEventDisableTiming);
        cudaEventCreateWithFlags(&ev_join, cudaEventDisableTiming);
    }

    cudaEventRecord(ev_fork, 0);
    cudaStreamWaitEvent(s2, ev_fork, 0);
    zero_counts_kernel<<<(NN + 255) / 256, 256, 0, s2>>>();
    hist_kernel<<<(NE + 255) / 256, 256, 0, s2>>>(edst);
    scan_kernel<<<1, 1024, 0, s2>>>();
    scatter_kernel<<<(NE + 255) / 256, 256, 0, s2>>>(esrc, edst, ew);
    cudaEventRecord(ev_join, s2);

    // single fused weight split on main stream
    split_w_all<<<(176128 + 255) / 256, 256>>>(W1, W2, W3, W4);

    const int GY = MP / 128;  // 782
    const int SPMM_BLOCKS = (NN * 32 + 255) / 256;

    // Layer 1 (fused fp32 split): 512 -> 256
    gemm_l1_kernel<<<dim3(4, GY), 256, GSMEM>>>(x, wh + WOFF1, suph);
    cudaStreamWaitEvent(0, ev_join, 0);
    spmm_vec_kernel<256><<<SPMM_BLOCKS, 256>>>(suph, b1, ah, al);

    gemm_hmma_kernel<<<dim3(2, GY), 256, GSMEM>>>(ah, al, wh + WOFF2, suph, 256, 128);
    spmm_vec_kernel<128><<<SPMM_BLOCKS, 256>>>(suph, b2, ah, al);

    gemm_hmma_kernel<<<dim3(1, GY), 256, GSMEM>>>(ah, al, wh + WOFF3, suph, 128, 64);
    spmm_vec_kernel<64><<<SPMM_BLOCKS, 256>>>(suph, b3, ah, al);

    gemm_hmma_kernel<<<dim3(1, GY), 256, GSMEM>>>(ah, al, wh + WOFF4, suph, 64, 40);
    spmm_lsm_kernel<<<SPMM_BLOCKS, 256>>>(suph, b4, out);
}

// round 11
// speedup vs baseline: 3.2883x; 1.0862x over previous
#include <cuda_runtime.h>
#include <cuda_fp16.h>
#include <cuda_bf16.h>
#include <cstdint>

#define NN 100000
#define NE 3200000
#define MP 100096   // 782 * 128 (padded rows)

// ================= scratch =================
__device__ uint16_t g_act[(size_t)MP * 256];    // fp16 activations (layers 2-4 input)
__device__ uint16_t g_suph[(size_t)MP * 256];   // fp16 support (GEMM out)
__device__ uint16_t g_wh[180224];               // fp16 Wt (all layers)
__device__ int   g_rowptr[NN + 1];
__device__ int   g_cursor[NN];
__device__ int   g_esrc[NE];
__device__ float g_ew[NE];

// ================= CSR build =================
__global__ void zero_counts_kernel() {
    int i = blockIdx.x * blockDim.x + threadIdx.x;
    if (i < NN) g_cursor[i] = 0;
}
__global__ void hist_kernel(const int* __restrict__ dst) {
    int e = blockIdx.x * blockDim.x + threadIdx.x;
    if (e < NE) atomicAdd(&g_cursor[dst[e]], 1);
}
__global__ void scan_kernel() {
    __shared__ int sdata[1024];
    const int T = 1024;
    const int CH = (NN + T - 1) / T;
    int t = threadIdx.x;
    int base = t * CH;
    int s = 0;
    for (int i = 0; i < CH; i++) { int idx = base + i; if (idx < NN) s += g_cursor[idx]; }
    sdata[t] = s;
    __syncthreads();
    for (int off = 1; off < T; off <<= 1) {
        int v = (t >= off) ? sdata[t - off] : 0;
        __syncthreads(); sdata[t] += v; __syncthreads();
    }
    int running = sdata[t] - s;
    for (int i = 0; i < CH; i++) {
        int idx = base + i;
        if (idx < NN) {
            int c = g_cursor[idx];
            g_rowptr[idx] = running;
            g_cursor[idx] = running;
            running += c;
        }
    }
    if (t == 0) g_rowptr[NN] = NE;
}
__global__ void scatter_kernel(const int* __restrict__ src, const int* __restrict__ dst,
                               const float* __restrict__ ew) {
    int e = blockIdx.x * blockDim.x + threadIdx.x;
    if (e < NE) {
        int d = dst[e];
        int pos = atomicAdd(&g_cursor[d], 1);
        g_esrc[pos] = src[e];
        g_ew[pos] = ew[e];
    }
}

// ================= fp16 split helpers =================
__device__ __forceinline__ void split2h(float f0, float f1, uint32_t& hi, uint32_t& lo) {
    __half h0 = __float2half_rn(f0), h1 = __float2half_rn(f1);
    float r0 = f0 - __half2float(h0), r1 = f1 - __half2float(h1);
    __half l0 = __float2half_rn(r0), l1 = __float2half_rn(r1);
    hi = (uint32_t)__half_raw(h0).x | ((uint32_t)__half_raw(h1).x << 16);
    lo = (uint32_t)__half_raw(l0).x | ((uint32_t)__half_raw(l1).x << 16);
}

// ===== combined weight transpose+convert: W[K,N] fp32 -> Wt[NPr,K] fp16, all 4 layers =====
__global__ void split_w_all(const float* __restrict__ W1, const float* __restrict__ W2,
                            const float* __restrict__ W3, const float* __restrict__ W4) {
    int i = blockIdx.x * blockDim.x + threadIdx.x;
    if (i >= 176128) return;
    const float* W; int K, N, off;
    if (i < 131072)      { W = W1; K = 512; N = 256; off = 0; }
    else if (i < 163840) { W = W2; K = 256; N = 128; off = 131072; }
    else if (i < 172032) { W = W3; K = 128; N = 64;  off = 163840; }
    else                 { W = W4; K = 64;  N = 40;  off = 172032; }
    int local = i - off;
    int n = local / K, k = local % K;
    float v = (n < N) ? W[(size_t)k * N + n] : 0.f;
    g_wh[i] = __half_raw(__float2half_rn(v)).x;
}

// ================= mma.sync / cp.async helpers =================
__device__ __forceinline__ uint32_t smem_u32(const void* p) {
    uint32_t a;
    asm("{ .reg .u64 t; cvta.to.shared.u64 t, %1; cvt.u32.u64 %0, t; }" : "=r"(a) : "l"(p));
    return a;
}
__device__ __forceinline__ void ldsm_x4(uint32_t* r, uint32_t addr) {
    asm volatile("ldmatrix.sync.aligned.m8n8.x4.shared.b16 {%0,%1,%2,%3}, [%4];"
                 : "=r"(r[0]), "=r"(r[1]), "=r"(r[2]), "=r"(r[3]) : "r"(addr));
}
__device__ __forceinline__ void ldsm_x2(uint32_t* r, uint32_t addr) {
    asm volatile("ldmatrix.sync.aligned.m8n8.x2.shared.b16 {%0,%1}, [%2];"
                 : "=r"(r[0]), "=r"(r[1]) : "r"(addr));
}
__device__ __forceinline__ void mma_f16(float* c, const uint32_t* a, const uint32_t* b) {
    asm volatile(
        "mma.sync.aligned.m16n8k16.row.col.f32.f16.f16.f32 "
        "{%0,%1,%2,%3}, {%4,%5,%6,%7}, {%8,%9}, {%0,%1,%2,%3};"
        : "+f"(c[0]), "+f"(c[1]), "+f"(c[2]), "+f"(c[3])
        : "r"(a[0]), "r"(a[1]), "r"(a[2]), "r"(a[3]), "r"(b[0]), "r"(b[1]));
}
__device__ __forceinline__ void cp16(uint32_t saddr, const void* gptr) {
    asm volatile("cp.async.cg.shared.global [%0], [%1], 16;" :: "r"(saddr), "l"(gptr));
}
__device__ __forceinline__ void cp_commit() { asm volatile("cp.async.commit_group;"); }
template <int N>
__device__ __forceinline__ void cp_wait() { asm volatile("cp.async.wait_group %0;" :: "n"(N)); }

// ---- layer-1 (2-term) stage layout: AH 16K | AL 16K | B 8K ----
#define L1_STAGE 40960
#define L1_OFF_AH 0
#define L1_OFF_AL 16384
#define L1_OFF_BH 32768
// ---- layers 2-4 (1-term) stage layout: A 16K | B 8K ----
#define G1_STAGE 24576
#define G1_OFF_A 0
#define G1_OFF_B 16384

#define GEMM_EPILOGUE(NOUT)                                                                \
    do {                                                                                   \
        const int gid = lane >> 2, tid4 = lane & 3;                                        \
        _Pragma("unroll")                                                                  \
        for (int mf = 0; mf < 4; ++mf) {                                                   \
            _Pragma("unroll")                                                              \
            for (int nf = 0; nf < 2; ++nf) {                                               \
                int col = nb0 + wn + nf * 8 + tid4 * 2;                                    \
                if (col < (NOUT)) {                                                        \
                    int m0 = row0 + wm + mf * 16 + gid;                                    \
                    __half2 h0 = __floats2half2_rn(acc[mf][nf][0], acc[mf][nf][1]);        \
                    __half2 h1 = __floats2half2_rn(acc[mf][nf][2], acc[mf][nf][3]);        \
                    *(__half2*)(sup + (size_t)m0 * (NOUT) + col) = h0;                     \
                    *(__half2*)(sup + (size_t)(m0 + 8) * (NOUT) + col) = h1;               \
                }                                                                          \
            }                                                                              \
        }                                                                                  \
    } while (0)

// ================= layers 2-4 HMMA GEMM: single-term fp16 A =================
__global__ __launch_bounds__(256)
void gemm_hmma_kernel(const uint16_t* __restrict__ A,
                      const uint16_t* __restrict__ Bh,
                      __half* __restrict__ sup, int K, int NOUT) {
    extern __shared__ __align__(128) char smem[];
    const uint32_t sb = smem_u32(smem);
    const int tid = threadIdx.x, wid = tid >> 5, lane = tid & 31;
    const int row0 = blockIdx.y * 128;
    const int nb0 = blockIdx.x * 64;
    const int wm = (wid & 1) * 64;
    const int wn = (wid >> 1) * 16;

    float acc[4][2][4];
#pragma unroll
    for (int i = 0; i < 4; i++)
#pragma unroll
        for (int j = 0; j < 2; j++)
#pragma unroll
            for (int q = 0; q < 4; q++) acc[i][j][q] = 0.f;

    const int a_row_l = lane & 15;
    const int a_chl = lane >> 4;
    const int b_row_l = lane & 7;
    const int b_chl = (lane >> 3) & 1;
    const int CH = K >> 6;

    auto load_stage = [&](int c, int buf) {
        const int kbase = c * 64;
        const uint32_t so_base = sb + buf * G1_STAGE;
#pragma unroll
        for (int i = tid; i < 1024; i += 256) {
            int r = i >> 3, cb = i & 7;
            size_t gidx = (size_t)(row0 + r) * K + kbase + cb * 8;
            uint32_t so = r * 128 + ((cb ^ (r & 7)) << 4);
            cp16(so_base + G1_OFF_A + so, A + gidx);
        }
#pragma unroll
        for (int i = tid; i < 512; i += 256) {
            int r = i >> 3, cb = i & 7;
            size_t gidx = (size_t)r * K + kbase + cb * 8;
            uint32_t so = r * 128 + ((cb ^ (r & 7)) << 4);
            cp16(so_base + G1_OFF_B + so, Bh + (size_t)nb0 * K + gidx);
        }
        cp_commit();
    };

    load_stage(0, 0);
    for (int c = 0; c < CH; ++c) {
        if (c + 1 < CH) { load_stage(c + 1, (c + 1) & 1); cp_wait<1>(); }
        else cp_wait<0>();
        __syncthreads();
        const uint32_t stb = sb + (c & 1) * G1_STAGE;
#pragma unroll
        for (int ks = 0; ks < 4; ++ks) {
            uint32_t ah[4][4], bh[2][2];
#pragma unroll
            for (int mf = 0; mf < 4; ++mf) {
                int r = wm + mf * 16 + a_row_l;
                uint32_t so = r * 128 + (((ks * 2 + a_chl) ^ (r & 7)) << 4);
                ldsm_x4(ah[mf], stb + G1_OFF_A + so);
            }
#pragma unroll
            for (int nf = 0; nf < 2; ++nf) {
                int r = wn + nf * 8 + b_row_l;
                uint32_t so = r * 128 + (((ks * 2 + b_chl) ^ (r & 7)) << 4);
                ldsm_x2(bh[nf], stb + G1_OFF_B + so);
            }
#pragma unroll
            for (int mf = 0; mf < 4; ++mf)
#pragma unroll
                for (int nf = 0; nf < 2; ++nf)
                    mma_f16(acc[mf][nf], ah[mf], bh[nf]);
        }
        __syncthreads();
    }
    GEMM_EPILOGUE(NOUT);
}

// ================= layer-1 GEMM: fused fp32->fp16 hi/lo split of x (2-term) ==========
__global__ __launch_bounds__(256)
void gemm_l1_kernel(const float* __restrict__ x,
                    const uint16_t* __restrict__ Bh,
                    __half* __restrict__ sup) {
    extern __shared__ __align__(128) char smem[];
    const uint32_t sb = smem_u32(smem);
    const int tid = threadIdx.x, wid = tid >> 5, lane = tid & 31;
    const int row0 = blockIdx.y * 128;
    const int nb0 = blockIdx.x * 64;
    const int wm = (wid & 1) * 64;
    const int wn = (wid >> 1) * 16;
    const int K = 512, NOUT = 256, CH = 8;

    float acc[4][2][4];
#pragma unroll
    for (int i = 0; i < 4; i++)
#pragma unroll
        for (int j = 0; j < 2; j++)
#pragma unroll
            for (int q = 0; q < 4; q++) acc[i][j][q] = 0.f;

    const int a_row_l = lane & 15;
    const int a_chl = lane >> 4;
    const int b_row_l = lane & 7;
    const int b_chl = (lane >> 3) & 1;

    float4 areg[4][2];

    auto load_a = [&](int c) {
        const int kbase = c * 64;
#pragma unroll
        for (int it = 0; it < 4; it++) {
            int i = tid + it * 256;
            int r = i >> 3, cb = i & 7;
            int grow = row0 + r;
            if (grow < NN) {
                const float* gp = x + (size_t)grow * K + kbase + cb * 8;
                areg[it][0] = *(const float4*)gp;
                areg[it][1] = *(const float4*)(gp + 4);
            } else {
                areg[it][0] = make_float4(0.f, 0.f, 0.f, 0.f);
                areg[it][1] = make_float4(0.f, 0.f, 0.f, 0.f);
            }
        }
    };
    auto store_a = [&](int buf) {
#pragma unroll
        for (int it = 0; it < 4; it++) {
            int i = tid + it * 256;
            int r = i >> 3, cb = i & 7;
            uint32_t so = r * 128 + ((cb ^ (r & 7)) << 4);
            float f[8] = {areg[it][0].x, areg[it][0].y, areg[it][0].z, areg[it][0].w,
                          areg[it][1].x, areg[it][1].y, areg[it][1].z, areg[it][1].w};
            uint32_t hi[4], lo[4];
#pragma unroll
            for (int q = 0; q < 4; q++) split2h(f[2 * q], f[2 * q + 1], hi[q], lo[q]);
            *(uint4*)(smem + buf * L1_STAGE + L1_OFF_AH + so) = make_uint4(hi[0], hi[1], hi[2], hi[3]);
            *(uint4*)(smem + buf * L1_STAGE + L1_OFF_AL + so) = make_uint4(lo[0], lo[1], lo[2], lo[3]);
        }
    };
    auto load_b = [&](int c, int buf) {
        const int kbase = c * 64;
        const uint32_t so_base = sb + buf * L1_STAGE;
#pragma unroll
        for (int i = tid; i < 512; i += 256) {
            int r = i >> 3, cb = i & 7;
            size_t gidx = (size_t)(nb0 + r) * K + kbase + cb * 8;
            uint32_t so = r * 128 + ((cb ^ (r & 7)) << 4);
            cp16(so_base + L1_OFF_BH + so, Bh + gidx);
        }
        cp_commit();
    };

    load_a(0);
    load_b(0, 0);
    store_a(0);
    cp_wait<0>();
    __syncthreads();

    for (int c = 0; c < CH; ++c) {
        if (c + 1 < CH) { load_a(c + 1); load_b(c + 1, (c + 1) & 1); }
        const uint32_t stb = sb + (c & 1) * L1_STAGE;
#pragma unroll
        for (int ks = 0; ks < 4; ++ks) {
            uint32_t ah[4][4], al[4][4], bh[2][2];
#pragma unroll
            for (int mf = 0; mf < 4; ++mf) {
                int r = wm + mf * 16 + a_row_l;
                uint32_t so = r * 128 + (((ks * 2 + a_chl) ^ (r & 7)) << 4);
                ldsm_x4(ah[mf], stb + L1_OFF_AH + so);
                ldsm_x4(al[mf], stb + L1_OFF_AL + so);
            }
#pragma unroll
            for (int nf = 0; nf < 2; ++nf) {
                int r = wn + nf * 8 + b_row_l;
                uint32_t so = r * 128 + (((ks * 2 + b_chl) ^ (r & 7)) << 4);
                ldsm_x2(bh[nf], stb + L1_OFF_BH + so);
            }
#pragma unroll
            for (int mf = 0; mf < 4; ++mf)
#pragma unroll
                for (int nf = 0; nf < 2; ++nf) {
                    mma_f16(acc[mf][nf], ah[mf], bh[nf]);
                    mma_f16(acc[mf][nf], al[mf], bh[nf]);
                }
        }
        if (c + 1 < CH) {
            store_a((c + 1) & 1);
            cp_wait<0>();
            __syncthreads();
        }
    }
    GEMM_EPILOGUE(NOUT);
}

// ====== SpMM gather (fp16 support, 16B/lane, x4 edge unroll), fp16 act out ======
template <int D>
__global__ void spmm_vec_kernel(const __half* __restrict__ sup, const float* __restrict__ bias,
                                __half* __restrict__ act) {
    constexpr int LPE = D / 8;
    constexpr int EPI = 32 / LPE;
    const int warp = (blockIdx.x * blockDim.x + threadIdx.x) >> 5;
    const int lane = threadIdx.x & 31;
    if (warp >= NN) return;
    const int sub = lane / LPE;
    const int seg = lane % LPE;

    float acc[8];
#pragma unroll
    for (int q = 0; q < 8; q++) acc[q] = 0.f;

    const int e0 = g_rowptr[warp];
    const int e1 = g_rowptr[warp + 1];
    int e = e0;
    for (; e + 4 * EPI <= e1; e += 4 * EPI) {
        int s[4]; float w[4]; uint4 v[4];
#pragma unroll
        for (int u = 0; u < 4; u++) {
            int me = e + u * EPI + sub;
            s[u] = g_esrc[me];
            w[u] = g_ew[me];
        }
#pragma unroll
        for (int u = 0; u < 4; u++)
            v[u] = *((const uint4*)(sup + (size_t)s[u] * D) + seg);
#pragma unroll
        for (int u = 0; u < 4; u++) {
            float2 f0 = __half22float2(*(__half2*)&v[u].x);
            float2 f1 = __half22float2(*(__half2*)&v[u].y);
            float2 f2 = __half22float2(*(__half2*)&v[u].z);
            float2 f3 = __half22float2(*(__half2*)&v[u].w);
            acc[0] += w[u] * f0.x; acc[1] += w[u] * f0.y;
            acc[2] += w[u] * f1.x; acc[3] += w[u] * f1.y;
            acc[4] += w[u] * f2.x; acc[5] += w[u] * f2.y;
            acc[6] += w[u] * f3.x; acc[7] += w[u] * f3.y;
        }
    }
    for (; e < e1; e += EPI) {
        int me = e + sub;
        if (me < e1) {
            int s = g_esrc[me];
            float w = g_ew[me];
            uint4 v = *((const uint4*)(sup + (size_t)s * D) + seg);
            float2 f0 = __half22float2(*(__half2*)&v.x);
            float2 f1 = __half22float2(*(__half2*)&v.y);
            float2 f2 = __half22float2(*(__half2*)&v.z);
            float2 f3 = __half22float2(*(__half2*)&v.w);
            acc[0] += w * f0.x; acc[1] += w * f0.y;
            acc[2] += w * f1.x; acc[3] += w * f1.y;
            acc[4] += w * f2.x; acc[5] += w * f2.y;
            acc[6] += w * f3.x; acc[7] += w * f3.y;
        }
    }
#pragma unroll
    for (int off = LPE; off < 32; off <<= 1)
#pragma unroll
        for (int q = 0; q < 8; q++)
            acc[q] += __shfl_xor_sync(0xFFFFFFFFu, acc[q], off);

    if (lane < LPE) {
        int col0 = lane * 8;
        uint32_t p[4];
#pragma unroll
        for (int q = 0; q < 8; q += 2) {
            float vx = fmaxf(acc[q] + bias[col0 + q], 0.f);
            float vy = fmaxf(acc[q + 1] + bias[col0 + q + 1], 0.f);
            __half2 h2 = __floats2half2_rn(vx, vy);
            p[q >> 1] = *(uint32_t*)&h2;
        }
        *(uint4*)(act + (size_t)warp * D + col0) = make_uint4(p[0], p[1], p[2], p[3]);
    }
}

// ======== last layer: SpMM (D=40) fused with relu + log-softmax -> d_out =========
__global__ void spmm_lsm_kernel(const __half* __restrict__ sup, const float* __restrict__ bias,
                                float* __restrict__ out) {
    const int warp = (blockIdx.x * blockDim.x + threadIdx.x) >> 5;
    const int lane = threadIdx.x & 31;
    if (warp >= NN) return;
    float ax = 0.f, ay = 0.f;
    const int e0 = g_rowptr[warp];
    const int e1 = g_rowptr[warp + 1];
    const bool act = lane < 20;
    int e = e0;
    for (; e + 4 <= e1; e += 4) {
        int s[4]; float w[4]; float2 f[4];
#pragma unroll
        for (int u = 0; u < 4; u++) { s[u] = g_esrc[e + u]; w[u] = g_ew[e + u]; }
#pragma unroll
        for (int u = 0; u < 4; u++)
            f[u] = act ? __half22float2(((const __half2*)(sup + (size_t)s[u] * 40))[lane])
                       : make_float2(0.f, 0.f);
#pragma unroll
        for (int u = 0; u < 4; u++) { ax += w[u] * f[u].x; ay += w[u] * f[u].y; }
    }
    for (; e < e1; e++) {
        int s = g_esrc[e];
        float w = g_ew[e];
        if (act) {
            float2 f = __half22float2(((const __half2*)(sup + (size_t)s * 40))[lane]);
            ax += w * f.x; ay += w * f.y;
        }
    }
    float vx = act ? fmaxf(ax + bias[2 * lane], 0.f) : -INFINITY;
    float vy = act ? fmaxf(ay + bias[2 * lane + 1], 0.f) : -INFINITY;
    float m = fmaxf(vx, vy);
#pragma unroll
    for (int off = 16; off > 0; off >>= 1)
        m = fmaxf(m, __shfl_xor_sync(0xFFFFFFFFu, m, off));
    float s = act ? (expf(vx - m) + expf(vy - m)) : 0.f;
#pragma unroll
    for (int off = 16; off > 0; off >>= 1)
        s += __shfl_xor_sync(0xFFFFFFFFu, s, off);
    float lse = logf(s) + m;
    if (act) {
        out[(size_t)warp * 40 + 2 * lane] = vx - lse;
        out[(size_t)warp * 40 + 2 * lane + 1] = vy - lse;
    }
}

// ================= launch =================
extern "C" void kernel_launch(void* const* d_in, const int* in_sizes, int n_in,
                              void* d_out, int out_size) {
    const float* x  = (const float*)d_in[0];
    const int* esrc = (const int*)d_in[1];
    const int* edst = (const int*)d_in[2];
    const float* ew = (const float*)d_in[3];
    const float* W1 = (const float*)d_in[4];
    const float* b1 = (const float*)d_in[5];
    const float* W2 = (const float*)d_in[6];
    const float* b2 = (const float*)d_in[7];
    const float* W3 = (const float*)d_in[8];
    const float* b3 = (const float*)d_in[9];
    const float* W4 = (const float*)d_in[10];
    const float* b4 = (const float*)d_in[11];
    float* out = (float*)d_out;

    uint16_t *act_u, *suph_u, *wh;
    cudaGetSymbolAddress((void**)&act_u, g_act);
    cudaGetSymbolAddress((void**)&suph_u, g_suph);
    cudaGetSymbolAddress((void**)&wh, g_wh);
    __half* act = (__half*)act_u;
    __half* suph = (__half*)suph_u;

    const int WOFF1 = 0, WOFF2 = 131072, WOFF3 = 163840, WOFF4 = 172032;

    cudaFuncSetAttribute(gemm_hmma_kernel, cudaFuncAttributeMaxDynamicSharedMemorySize, 2 * G1_STAGE);
    cudaFuncSetAttribute(gemm_l1_kernel, cudaFuncAttributeMaxDynamicSharedMemorySize, 2 * L1_STAGE);

    static cudaStream_t s2 = nullptr;
    static cudaEvent_t ev_fork = nullptr, ev_join = nullptr;
    if (!s2) {
        cudaStreamCreateWithFlags(&s2, cudaStreamNonBlocking);
        cudaEventCreateWithFlags(&ev_fork, cudaEventDisableTiming);
        cudaEventCreateWithFlags(&ev_join, cudaEventDisableTiming);
    }

    cudaEventRecord(ev_fork, 0);
    cudaStreamWaitEvent(s2, ev_fork, 0);
    zero_counts_kernel<<<(NN + 255) / 256, 256, 0, s2>>>();
    hist_kernel<<<(NE + 255) / 256, 256, 0, s2>>>(edst);
    scan_kernel<<<1, 1024, 0, s2>>>();
    scatter_kernel<<<(NE + 255) / 256, 256, 0, s2>>>(esrc, edst, ew);
    cudaEventRecord(ev_join, s2);

    split_w_all<<<(176128 + 255) / 256, 256>>>(W1, W2, W3, W4);

    const int GY = MP / 128;  // 782
    const int SPMM_BLOCKS = (NN * 32 + 255) / 256;

    // Layer 1 (fused fp32 split, 2-term): 512 -> 256
    gemm_l1_kernel<<<dim3(4, GY), 256, 2 * L1_STAGE>>>(x, wh + WOFF1, suph);
    cudaStreamWaitEvent(0, ev_join, 0);
    spmm_vec_kernel<256><<<SPMM_BLOCKS, 256>>>(suph, b1, act);

    gemm_hmma_kernel<<<dim3(2, GY), 256, 2 * G1_STAGE>>>(act_u, wh + WOFF2, suph, 256, 128);
    spmm_vec_kernel<128><<<SPMM_BLOCKS, 256>>>(suph, b2, act);

    gemm_hmma_kernel<<<dim3(1, GY), 256, 2 * G1_STAGE>>>(act_u, wh + WOFF3, suph, 128, 64);
    spmm_vec_kernel<64><<<SPMM_BLOCKS, 256>>>(suph, b3, act);

    gemm_hmma_kernel<<<dim3(1, GY), 256, 2 * G1_STAGE>>>(act_u, wh + WOFF4, suph, 64, 40);
    spmm_lsm_kernel<<<SPMM_BLOCKS, 256>>>(suph, b4, out);
}